// round 5
// baseline (speedup 1.0000x reference)
#include <cuda_runtime.h>

#define NN 100000
#define NE 1600000
#define DD 128
#define HH 32
#define NL 4

// ---- scratch (static device memory; no allocation) ----
__device__ __align__(16) float g_Z[NN * DD];   // aggregation buffer (primed with (1+eps)X)
__device__ __align__(16) float g_XA[NN * DD];  // ping
__device__ __align__(16) float g_XB[NN * DD];  // pong
__device__ __align__(16) float g_Y1[NN * HH];
__device__ __align__(16) float g_Y2[NN * HH];
__device__ double g_stats1[2 * HH];            // [0..31] sum, [32..63] sumsq
__device__ double g_stats2[2 * HH];
__device__ float g_bnA1[HH], g_bnC1[HH], g_bnA2[HH], g_bnC2[HH];
__device__ int g_ei64;                         // 1 if edge_index is int64, 0 if int32

// ---------------------------------------------------------------------------
// Detect edge_index dtype: if the buffer is int64 all entries are in [0, NN).
// If it's int32, reinterpreting pairs as int64 gives values >= 2^32 almost surely.
// ---------------------------------------------------------------------------
__global__ void k_detect(const long long* __restrict__ ei) {
    if (threadIdx.x == 0 && blockIdx.x == 0) {
        int is64 = 1;
        for (int i = 0; i < 16; i++) {
            long long v = ei[i];
            if (v < 0 || v >= (long long)NN) { is64 = 0; break; }
        }
        g_ei64 = is64;
    }
}

// ---------------------------------------------------------------------------
// Layer-0 init: Z = (1+eps[0]) * X_in ; zero stats
// ---------------------------------------------------------------------------
__global__ void k_init(const float4* __restrict__ X, const float* __restrict__ eps) {
    if (blockIdx.x == 0) {
        int t = threadIdx.x;
        if (t < 64) g_stats1[t] = 0.0;
        else if (t < 128) g_stats2[t - 64] = 0.0;
    }
    float s = 1.0f + eps[0];
    float4* Z4 = (float4*)g_Z;
    int total = NN * DD / 4;
    for (int i = blockIdx.x * blockDim.x + threadIdx.x; i < total;
         i += gridDim.x * blockDim.x) {
        float4 v = X[i];
        v.x *= s; v.y *= s; v.z *= s; v.w *= s;
        Z4[i] = v;
    }
}

// ---------------------------------------------------------------------------
// Scatter-add: for each edge, Z[dst] += X[src]. Warp per edge, lane = float4.
// xsel: 0 = external input pointer, 1 = g_XA, 2 = g_XB
// ---------------------------------------------------------------------------
__global__ void k_scatter(const float4* __restrict__ Xin,
                          const long long* __restrict__ ei, int xsel) {
    const float4* X = (xsel == 0) ? Xin
                    : (xsel == 1) ? (const float4*)g_XA
                                  : (const float4*)g_XB;
    const int* ei32 = (const int*)ei;
    const int is64 = g_ei64;
    int gtid = blockIdx.x * blockDim.x + threadIdx.x;
    int warp = gtid >> 5;
    int lane = gtid & 31;
    int nw = (gridDim.x * blockDim.x) >> 5;
    float4* Z4 = (float4*)g_Z;
    for (int e = warp; e < NE; e += nw) {
        int src, dst;
        if (is64) {
            src = (int)ei[e];
            dst = (int)ei[NE + e];
        } else {
            src = ei32[e];
            dst = ei32[NE + e];
        }
        float4 v = __ldg(&X[src * (DD / 4) + lane]);
        float4* p = Z4 + dst * (DD / 4) + lane;
        asm volatile("red.global.add.v4.f32 [%0], {%1, %2, %3, %4};"
                     :: "l"(p), "f"(v.x), "f"(v.y), "f"(v.z), "f"(v.w)
                     : "memory");
    }
}

// ---------------------------------------------------------------------------
// GEMM1: Y1 = Z @ W1^T + b1  (K=128 -> 32), accumulate column sum/sumsq
// Warp per row; lane = output column; W1 tile in smem (transposed, padded).
// ---------------------------------------------------------------------------
__global__ __launch_bounds__(256) void k_gemm1(const float* __restrict__ W1l,
                                               const float* __restrict__ b1l) {
    __shared__ __align__(16) float Ws[DD * (HH + 1)];
    __shared__ float ssum[8][HH], ssq[8][HH];
    for (int i = threadIdx.x; i < DD * HH; i += blockDim.x) {
        int c = i & 31;
        int k = i >> 5;
        Ws[k * (HH + 1) + c] = W1l[c * DD + k];
    }
    __syncthreads();
    int warp = threadIdx.x >> 5;
    int lane = threadIdx.x & 31;
    int gw = blockIdx.x * 8 + warp;
    int nw = gridDim.x * 8;
    const float4* Z4 = (const float4*)g_Z;
    float bias = b1l[lane];
    float lsum = 0.f, lsq = 0.f;
    for (int r = gw; r < NN; r += nw) {
        float4 zv = Z4[r * 32 + lane];
        float acc = bias;
#pragma unroll
        for (int kk = 0; kk < 32; kk++) {
            float z0 = __shfl_sync(0xffffffffu, zv.x, kk);
            float z1 = __shfl_sync(0xffffffffu, zv.y, kk);
            float z2 = __shfl_sync(0xffffffffu, zv.z, kk);
            float z3 = __shfl_sync(0xffffffffu, zv.w, kk);
            int k = kk * 4;
            acc = fmaf(z0, Ws[(k + 0) * (HH + 1) + lane], acc);
            acc = fmaf(z1, Ws[(k + 1) * (HH + 1) + lane], acc);
            acc = fmaf(z2, Ws[(k + 2) * (HH + 1) + lane], acc);
            acc = fmaf(z3, Ws[(k + 3) * (HH + 1) + lane], acc);
        }
        g_Y1[r * HH + lane] = acc;
        lsum += acc;
        lsq = fmaf(acc, acc, lsq);
    }
    ssum[warp][lane] = lsum;
    ssq[warp][lane] = lsq;
    __syncthreads();
    if (threadIdx.x < HH) {
        float s = 0.f, q = 0.f;
        for (int w = 0; w < 8; w++) { s += ssum[w][threadIdx.x]; q += ssq[w][threadIdx.x]; }
        atomicAdd(&g_stats1[threadIdx.x], (double)s);
        atomicAdd(&g_stats1[HH + threadIdx.x], (double)q);
    }
}

// ---------------------------------------------------------------------------
// BN param fold: a = g*rsqrt(var+eps), c = bt - a*mean ; zero the other stats
// ---------------------------------------------------------------------------
__global__ void k_bn(int which, const float* __restrict__ g,
                     const float* __restrict__ bt) {
    int c = threadIdx.x;
    if (c >= HH) return;
    const double* st = (which == 1) ? g_stats1 : g_stats2;
    float* A = (which == 1) ? g_bnA1 : g_bnA2;
    float* C = (which == 1) ? g_bnC1 : g_bnC2;
    double* zs = (which == 1) ? g_stats2 : g_stats1;
    double mean = st[c] / (double)NN;
    double var = st[HH + c] / (double)NN - mean * mean;
    float a = g[c] * rsqrtf((float)var + 1e-5f);
    A[c] = a;
    C[c] = bt[c] - a * (float)mean;
    zs[c] = 0.0;
    zs[HH + c] = 0.0;
}

// ---------------------------------------------------------------------------
// GEMM2: h = relu(bn1(Y1)); Y2 = h @ W2^T + b2  (32 -> 32), accumulate stats2
// ---------------------------------------------------------------------------
__global__ __launch_bounds__(256) void k_gemm2(const float* __restrict__ W2l,
                                               const float* __restrict__ b2l) {
    __shared__ __align__(16) float Ws[HH * (HH + 1)];
    __shared__ float ssum[8][HH], ssq[8][HH];
    for (int i = threadIdx.x; i < HH * HH; i += blockDim.x) {
        int c = i & 31;
        int k = i >> 5;
        Ws[k * (HH + 1) + c] = W2l[c * HH + k];
    }
    __syncthreads();
    int warp = threadIdx.x >> 5;
    int lane = threadIdx.x & 31;
    int gw = blockIdx.x * 8 + warp;
    int nw = gridDim.x * 8;
    float a = g_bnA1[lane];
    float cs = g_bnC1[lane];
    float bias = b2l[lane];
    float lsum = 0.f, lsq = 0.f;
    for (int r = gw; r < NN; r += nw) {
        float y = g_Y1[r * HH + lane];
        float h = fmaxf(fmaf(a, y, cs), 0.0f);
        float acc = bias;
#pragma unroll
        for (int k = 0; k < HH; k++) {
            float hk = __shfl_sync(0xffffffffu, h, k);
            acc = fmaf(hk, Ws[k * (HH + 1) + lane], acc);
        }
        g_Y2[r * HH + lane] = acc;
        lsum += acc;
        lsq = fmaf(acc, acc, lsq);
    }
    ssum[warp][lane] = lsum;
    ssq[warp][lane] = lsq;
    __syncthreads();
    if (threadIdx.x < HH) {
        float s = 0.f, q = 0.f;
        for (int w = 0; w < 8; w++) { s += ssum[w][threadIdx.x]; q += ssq[w][threadIdx.x]; }
        atomicAdd(&g_stats2[threadIdx.x], (double)s);
        atomicAdd(&g_stats2[HH + threadIdx.x], (double)q);
    }
}

// ---------------------------------------------------------------------------
// GEMM3: h = relu(bn2(Y2)); X_next = h @ W3^T + b3  (32 -> 128)
// Also primes Z_next = (1+eps[next_l])*X_next when next_l >= 0.
// osel: 1 = g_XA, 2 = g_XB, 3 = external out pointer
// ---------------------------------------------------------------------------
__global__ __launch_bounds__(256) void k_gemm3(const float* __restrict__ W3l,
                                               const float* __restrict__ b3l,
                                               float4* __restrict__ Xext, int osel,
                                               const float* __restrict__ eps,
                                               int next_l) {
    __shared__ __align__(16) float Wt[HH * DD];  // Wt[k*128 + o] = W3l[o*32 + k]
    for (int i = threadIdx.x; i < HH * DD; i += blockDim.x) {
        int o = i >> 5;
        int k = i & 31;
        Wt[k * DD + o] = W3l[i];
    }
    __syncthreads();
    float4* Xout = (osel == 1) ? (float4*)g_XA
                 : (osel == 2) ? (float4*)g_XB
                               : Xext;
    int warp = threadIdx.x >> 5;
    int lane = threadIdx.x & 31;
    int gw = blockIdx.x * 8 + warp;
    int nw = gridDim.x * 8;
    float a = g_bnA2[lane];
    float cs = g_bnC2[lane];
    float4 bias = ((const float4*)b3l)[lane];
    bool hn = (next_l >= 0);
    float s = hn ? (1.0f + eps[next_l]) : 0.0f;
    float4* Z4 = (float4*)g_Z;
    const float4* Wt4 = (const float4*)Wt;
    for (int r = gw; r < NN; r += nw) {
        float y = g_Y2[r * HH + lane];
        float h = fmaxf(fmaf(a, y, cs), 0.0f);
        float4 acc = bias;
#pragma unroll
        for (int k = 0; k < HH; k++) {
            float hk = __shfl_sync(0xffffffffu, h, k);
            float4 w = Wt4[k * 32 + lane];
            acc.x = fmaf(hk, w.x, acc.x);
            acc.y = fmaf(hk, w.y, acc.y);
            acc.z = fmaf(hk, w.z, acc.z);
            acc.w = fmaf(hk, w.w, acc.w);
        }
        Xout[r * 32 + lane] = acc;
        if (hn) {
            float4 z;
            z.x = acc.x * s; z.y = acc.y * s; z.z = acc.z * s; z.w = acc.w * s;
            Z4[r * 32 + lane] = z;
        }
    }
}

// ---------------------------------------------------------------------------
extern "C" void kernel_launch(void* const* d_in, const int* in_sizes, int n_in,
                              void* d_out, int out_size) {
    const float* X = (const float*)d_in[0];
    const long long* ei = (const long long*)d_in[1];
    const float* eps = (const float*)d_in[2];
    const float* W1 = (const float*)d_in[3];
    const float* b1 = (const float*)d_in[4];
    const float* g1 = (const float*)d_in[5];
    const float* bt1 = (const float*)d_in[6];
    const float* W2 = (const float*)d_in[7];
    const float* b2 = (const float*)d_in[8];
    const float* g2 = (const float*)d_in[9];
    const float* bt2 = (const float*)d_in[10];
    const float* W3 = (const float*)d_in[11];
    const float* b3 = (const float*)d_in[12];

    const int GB = 592;   // GEMM grid (4 * 148)
    const int SB = 2048;  // scatter grid

    k_detect<<<1, 32>>>(ei);
    k_init<<<4096, 256>>>((const float4*)X, eps);

    // xsel per layer: which buffer holds the current X (for scatter)
    // osel per layer: where gemm3 writes X_next
    int xsel[NL] = {0, 1, 2, 1};
    int osel[NL] = {1, 2, 1, 3};

    for (int l = 0; l < NL; l++) {
        k_scatter<<<SB, 256>>>((const float4*)X, ei, xsel[l]);
        k_gemm1<<<GB, 256>>>(W1 + l * HH * DD, b1 + l * HH);
        k_bn<<<1, 32>>>(1, g1 + l * HH, bt1 + l * HH);
        k_gemm2<<<GB, 256>>>(W2 + l * HH * HH, b2 + l * HH);
        k_bn<<<1, 32>>>(2, g2 + l * HH, bt2 + l * HH);
        int next_l = (l < NL - 1) ? (l + 1) : -1;
        k_gemm3<<<GB, 256>>>(W3 + l * DD * HH, b3 + l * DD,
                             (float4*)d_out, osel[l], eps, next_l);
    }
}

// round 7
// speedup vs baseline: 1.1243x; 1.1243x over previous
#include <cuda_runtime.h>

#define NN 100000
#define NE 1600000
#define DD 128
#define HH 32
#define NL 4

// ---- scratch (static device memory; no allocation) ----
__device__ __align__(16) float g_Z[NN * DD];   // aggregation buffer (primed with (1+eps)X)
__device__ __align__(16) float g_XA[NN * DD];  // ping
__device__ __align__(16) float g_XB[NN * DD];  // pong
__device__ __align__(16) float g_Y1[NN * HH];
__device__ __align__(16) float g_Y2[NN * HH];
__device__ double g_stats1[2 * HH];            // [0..31] sum, [32..63] sumsq
__device__ double g_stats2[2 * HH];
__device__ __align__(16) float g_bnA1[HH], g_bnC1[HH], g_bnA2[HH], g_bnC2[HH];
__device__ int g_ei64;                         // 1 if edge_index is int64, 0 if int32

// ---------------------------------------------------------------------------
// Detect edge_index dtype (int64 vs silently-downgraded int32).
// ---------------------------------------------------------------------------
__global__ void k_detect(const long long* __restrict__ ei) {
    if (threadIdx.x == 0 && blockIdx.x == 0) {
        int is64 = 1;
        for (int i = 0; i < 16; i++) {
            long long v = ei[i];
            if (v < 0 || v >= (long long)NN) { is64 = 0; break; }
        }
        g_ei64 = is64;
    }
}

// ---------------------------------------------------------------------------
// Layer-0 init: Z = (1+eps[0]) * X_in ; zero stats
// ---------------------------------------------------------------------------
__global__ void k_init(const float4* __restrict__ X, const float* __restrict__ eps) {
    if (blockIdx.x == 0) {
        int t = threadIdx.x;
        if (t < 64) g_stats1[t] = 0.0;
        else if (t < 128) g_stats2[t - 64] = 0.0;
    }
    float s = 1.0f + eps[0];
    float4* Z4 = (float4*)g_Z;
    int total = NN * DD / 4;
    for (int i = blockIdx.x * blockDim.x + threadIdx.x; i < total;
         i += gridDim.x * blockDim.x) {
        float4 v = X[i];
        v.x *= s; v.y *= s; v.z *= s; v.w *= s;
        Z4[i] = v;
    }
}

// ---------------------------------------------------------------------------
// Scatter-add: warp per edge, lane = float4 chunk. red.global.add.v4.f32.
// ---------------------------------------------------------------------------
__global__ void k_scatter(const float4* __restrict__ Xin,
                          const long long* __restrict__ ei, int xsel) {
    const float4* X = (xsel == 0) ? Xin
                    : (xsel == 1) ? (const float4*)g_XA
                                  : (const float4*)g_XB;
    const int* ei32 = (const int*)ei;
    const int is64 = g_ei64;
    int gtid = blockIdx.x * blockDim.x + threadIdx.x;
    int warp = gtid >> 5;
    int lane = gtid & 31;
    int nw = (gridDim.x * blockDim.x) >> 5;
    float4* Z4 = (float4*)g_Z;
    for (int e = warp; e < NE; e += nw) {
        int src, dst;
        if (is64) {
            src = (int)ei[e];
            dst = (int)ei[NE + e];
        } else {
            src = ei32[e];
            dst = ei32[NE + e];
        }
        float4 v = __ldg(&X[src * (DD / 4) + lane]);
        float4* p = Z4 + dst * (DD / 4) + lane;
        asm volatile("red.global.add.v4.f32 [%0], {%1, %2, %3, %4};"
                     :: "l"(p), "f"(v.x), "f"(v.y), "f"(v.z), "f"(v.w)
                     : "memory");
    }
}

// ---------------------------------------------------------------------------
// GEMM1: Y1 = Z @ W1^T + b1  (K=128 -> 32) + column stats.
// Warp = 4 rows; thread = (row-slot r=lane>>3, col-group c4=lane&7, 4 cols).
// 1 SHFL feeds 4 FMAs; 1 LDS.128 feeds 4 FMAs.
// ---------------------------------------------------------------------------
__global__ __launch_bounds__(256) void k_gemm1(const float* __restrict__ W1l,
                                               const float* __restrict__ b1l) {
    __shared__ __align__(16) float Ws[DD * HH];  // Ws[k*32 + c] = W1l[c*128 + k]
    __shared__ float bsum[HH], bsq[HH];
    for (int i = threadIdx.x; i < DD * HH; i += 256) {
        int k = i >> 5, c = i & 31;
        Ws[k * 32 + c] = W1l[c * DD + k];
    }
    if (threadIdx.x < HH) { bsum[threadIdx.x] = 0.f; bsq[threadIdx.x] = 0.f; }
    __syncthreads();
    const float4* Ws4 = (const float4*)Ws;     // Ws4[k*8 + c4]
    int lane = threadIdx.x & 31;
    int r = lane >> 3, c4 = lane & 7, base = lane & 24;
    int gw = blockIdx.x * 8 + (threadIdx.x >> 5);
    int nw = gridDim.x * 8;
    const float4* Z4 = (const float4*)g_Z;
    float4 bias = ((const float4*)b1l)[c4];
    float4 ls = {0, 0, 0, 0}, lq = {0, 0, 0, 0};
    for (int rb = gw * 4; rb < NN; rb += nw * 4) {
        int row = rb + r;
        const float4* zp = Z4 + row * 32 + c4;
        float4 z0 = zp[0], z1 = zp[8], z2 = zp[16], z3 = zp[24];
        float4 acc = bias;
#pragma unroll
        for (int f = 0; f < 32; f++) {
            float4 zz = (f < 8) ? z0 : (f < 16) ? z1 : (f < 24) ? z2 : z3;
            int srcl = base | (f & 7);
            float a0 = __shfl_sync(0xffffffffu, zz.x, srcl);
            float a1 = __shfl_sync(0xffffffffu, zz.y, srcl);
            float a2 = __shfl_sync(0xffffffffu, zz.z, srcl);
            float a3 = __shfl_sync(0xffffffffu, zz.w, srcl);
            float4 w0 = Ws4[(4 * f + 0) * 8 + c4];
            float4 w1 = Ws4[(4 * f + 1) * 8 + c4];
            float4 w2 = Ws4[(4 * f + 2) * 8 + c4];
            float4 w3 = Ws4[(4 * f + 3) * 8 + c4];
            acc.x = fmaf(a0, w0.x, fmaf(a1, w1.x, fmaf(a2, w2.x, fmaf(a3, w3.x, acc.x))));
            acc.y = fmaf(a0, w0.y, fmaf(a1, w1.y, fmaf(a2, w2.y, fmaf(a3, w3.y, acc.y))));
            acc.z = fmaf(a0, w0.z, fmaf(a1, w1.z, fmaf(a2, w2.z, fmaf(a3, w3.z, acc.z))));
            acc.w = fmaf(a0, w0.w, fmaf(a1, w1.w, fmaf(a2, w2.w, fmaf(a3, w3.w, acc.w))));
        }
        ((float4*)g_Y1)[row * 8 + c4] = acc;
        ls.x += acc.x; ls.y += acc.y; ls.z += acc.z; ls.w += acc.w;
        lq.x = fmaf(acc.x, acc.x, lq.x); lq.y = fmaf(acc.y, acc.y, lq.y);
        lq.z = fmaf(acc.z, acc.z, lq.z); lq.w = fmaf(acc.w, acc.w, lq.w);
    }
    atomicAdd(&bsum[4 * c4 + 0], ls.x); atomicAdd(&bsum[4 * c4 + 1], ls.y);
    atomicAdd(&bsum[4 * c4 + 2], ls.z); atomicAdd(&bsum[4 * c4 + 3], ls.w);
    atomicAdd(&bsq[4 * c4 + 0], lq.x);  atomicAdd(&bsq[4 * c4 + 1], lq.y);
    atomicAdd(&bsq[4 * c4 + 2], lq.z);  atomicAdd(&bsq[4 * c4 + 3], lq.w);
    __syncthreads();
    if (threadIdx.x < HH) {
        atomicAdd(&g_stats1[threadIdx.x], (double)bsum[threadIdx.x]);
        atomicAdd(&g_stats1[HH + threadIdx.x], (double)bsq[threadIdx.x]);
    }
}

// ---------------------------------------------------------------------------
// BN param fold: a = g*rsqrt(var+eps), c = bt - a*mean ; zero the other stats
// ---------------------------------------------------------------------------
__global__ void k_bn(int which, const float* __restrict__ g,
                     const float* __restrict__ bt) {
    int c = threadIdx.x;
    if (c >= HH) return;
    const double* st = (which == 1) ? g_stats1 : g_stats2;
    float* A = (which == 1) ? g_bnA1 : g_bnA2;
    float* C = (which == 1) ? g_bnC1 : g_bnC2;
    double* zs = (which == 1) ? g_stats2 : g_stats1;
    double mean = st[c] / (double)NN;
    double var = st[HH + c] / (double)NN - mean * mean;
    float a = g[c] * rsqrtf((float)var + 1e-5f);
    A[c] = a;
    C[c] = bt[c] - a * (float)mean;
    zs[c] = 0.0;
    zs[HH + c] = 0.0;
}

// ---------------------------------------------------------------------------
// GEMM2: h = relu(bn1(Y1)); Y2 = h @ W2^T + b2  (32 -> 32) + stats2.
// Same 4-rows-per-warp scheme.
// ---------------------------------------------------------------------------
__global__ __launch_bounds__(256) void k_gemm2(const float* __restrict__ W2l,
                                               const float* __restrict__ b2l) {
    __shared__ __align__(16) float Ws[HH * HH];  // Ws[k*32 + c] = W2l[c*32 + k]
    __shared__ float bsum[HH], bsq[HH];
    for (int i = threadIdx.x; i < HH * HH; i += 256) {
        int k = i >> 5, c = i & 31;
        Ws[k * 32 + c] = W2l[c * HH + k];
    }
    if (threadIdx.x < HH) { bsum[threadIdx.x] = 0.f; bsq[threadIdx.x] = 0.f; }
    __syncthreads();
    const float4* Ws4 = (const float4*)Ws;
    int lane = threadIdx.x & 31;
    int r = lane >> 3, c4 = lane & 7, base = lane & 24;
    int gw = blockIdx.x * 8 + (threadIdx.x >> 5);
    int nw = gridDim.x * 8;
    float4 bias = ((const float4*)b2l)[c4];
    float4 ba = ((const float4*)g_bnA1)[c4];
    float4 bc = ((const float4*)g_bnC1)[c4];
    float4 ls = {0, 0, 0, 0}, lq = {0, 0, 0, 0};
    for (int rb = gw * 4; rb < NN; rb += nw * 4) {
        int row = rb + r;
        float4 y = ((const float4*)g_Y1)[row * 8 + c4];
        float4 h;
        h.x = fmaxf(fmaf(ba.x, y.x, bc.x), 0.f);
        h.y = fmaxf(fmaf(ba.y, y.y, bc.y), 0.f);
        h.z = fmaxf(fmaf(ba.z, y.z, bc.z), 0.f);
        h.w = fmaxf(fmaf(ba.w, y.w, bc.w), 0.f);
        float4 acc = bias;
#pragma unroll
        for (int f = 0; f < 8; f++) {
            int srcl = base | f;
            float a0 = __shfl_sync(0xffffffffu, h.x, srcl);
            float a1 = __shfl_sync(0xffffffffu, h.y, srcl);
            float a2 = __shfl_sync(0xffffffffu, h.z, srcl);
            float a3 = __shfl_sync(0xffffffffu, h.w, srcl);
            float4 w0 = Ws4[(4 * f + 0) * 8 + c4];
            float4 w1 = Ws4[(4 * f + 1) * 8 + c4];
            float4 w2 = Ws4[(4 * f + 2) * 8 + c4];
            float4 w3 = Ws4[(4 * f + 3) * 8 + c4];
            acc.x = fmaf(a0, w0.x, fmaf(a1, w1.x, fmaf(a2, w2.x, fmaf(a3, w3.x, acc.x))));
            acc.y = fmaf(a0, w0.y, fmaf(a1, w1.y, fmaf(a2, w2.y, fmaf(a3, w3.y, acc.y))));
            acc.z = fmaf(a0, w0.z, fmaf(a1, w1.z, fmaf(a2, w2.z, fmaf(a3, w3.z, acc.z))));
            acc.w = fmaf(a0, w0.w, fmaf(a1, w1.w, fmaf(a2, w2.w, fmaf(a3, w3.w, acc.w))));
        }
        ((float4*)g_Y2)[row * 8 + c4] = acc;
        ls.x += acc.x; ls.y += acc.y; ls.z += acc.z; ls.w += acc.w;
        lq.x = fmaf(acc.x, acc.x, lq.x); lq.y = fmaf(acc.y, acc.y, lq.y);
        lq.z = fmaf(acc.z, acc.z, lq.z); lq.w = fmaf(acc.w, acc.w, lq.w);
    }
    atomicAdd(&bsum[4 * c4 + 0], ls.x); atomicAdd(&bsum[4 * c4 + 1], ls.y);
    atomicAdd(&bsum[4 * c4 + 2], ls.z); atomicAdd(&bsum[4 * c4 + 3], ls.w);
    atomicAdd(&bsq[4 * c4 + 0], lq.x);  atomicAdd(&bsq[4 * c4 + 1], lq.y);
    atomicAdd(&bsq[4 * c4 + 2], lq.z);  atomicAdd(&bsq[4 * c4 + 3], lq.w);
    __syncthreads();
    if (threadIdx.x < HH) {
        atomicAdd(&g_stats2[threadIdx.x], (double)bsum[threadIdx.x]);
        atomicAdd(&g_stats2[HH + threadIdx.x], (double)bsq[threadIdx.x]);
    }
}

// ---------------------------------------------------------------------------
// GEMM3: h = relu(bn2(Y2)); X_next = h @ W3^T + b3  (32 -> 128)
// Thread covers 16 outputs (4 col-chunks of 4). Also primes Z_next.
// ---------------------------------------------------------------------------
__global__ __launch_bounds__(256) void k_gemm3(const float* __restrict__ W3l,
                                               const float* __restrict__ b3l,
                                               float4* __restrict__ Xext, int osel,
                                               const float* __restrict__ eps,
                                               int next_l) {
    __shared__ __align__(16) float Wt[HH * DD];  // Wt[k*128 + c] = W3l[c*32 + k]
    for (int i = threadIdx.x; i < HH * DD; i += 256) {
        int c = i >> 5, k = i & 31;
        Wt[k * DD + c] = W3l[i];
    }
    __syncthreads();
    const float4* Wt4 = (const float4*)Wt;      // Wt4[k*32 + (c>>2)]
    float4* Xout = (osel == 1) ? (float4*)g_XA
                 : (osel == 2) ? (float4*)g_XB
                               : Xext;
    int lane = threadIdx.x & 31;
    int r = lane >> 3, c4 = lane & 7, base = lane & 24;
    int gw = blockIdx.x * 8 + (threadIdx.x >> 5);
    int nw = gridDim.x * 8;
    float4 ba = ((const float4*)g_bnA2)[c4];
    float4 bc = ((const float4*)g_bnC2)[c4];
    float4 bias0 = ((const float4*)b3l)[c4 + 0];
    float4 bias1 = ((const float4*)b3l)[c4 + 8];
    float4 bias2 = ((const float4*)b3l)[c4 + 16];
    float4 bias3 = ((const float4*)b3l)[c4 + 24];
    bool hn = (next_l >= 0);
    float s = hn ? (1.0f + eps[next_l]) : 0.0f;
    float4* Z4 = (float4*)g_Z;
    for (int rb = gw * 4; rb < NN; rb += nw * 4) {
        int row = rb + r;
        float4 y = ((const float4*)g_Y2)[row * 8 + c4];
        float4 h;
        h.x = fmaxf(fmaf(ba.x, y.x, bc.x), 0.f);
        h.y = fmaxf(fmaf(ba.y, y.y, bc.y), 0.f);
        h.z = fmaxf(fmaf(ba.z, y.z, bc.z), 0.f);
        h.w = fmaxf(fmaf(ba.w, y.w, bc.w), 0.f);
        float4 acc0 = bias0, acc1 = bias1, acc2 = bias2, acc3 = bias3;
#pragma unroll
        for (int f = 0; f < 8; f++) {
            int srcl = base | f;
            float a0 = __shfl_sync(0xffffffffu, h.x, srcl);
            float a1 = __shfl_sync(0xffffffffu, h.y, srcl);
            float a2 = __shfl_sync(0xffffffffu, h.z, srcl);
            float a3 = __shfl_sync(0xffffffffu, h.w, srcl);
#pragma unroll
            for (int u = 0; u < 4; u++) {
                float4* accp = (u == 0) ? &acc0 : (u == 1) ? &acc1 : (u == 2) ? &acc2 : &acc3;
                float4 w0 = Wt4[(4 * f + 0) * 32 + c4 + 8 * u];
                float4 w1 = Wt4[(4 * f + 1) * 32 + c4 + 8 * u];
                float4 w2 = Wt4[(4 * f + 2) * 32 + c4 + 8 * u];
                float4 w3 = Wt4[(4 * f + 3) * 32 + c4 + 8 * u];
                accp->x = fmaf(a0, w0.x, fmaf(a1, w1.x, fmaf(a2, w2.x, fmaf(a3, w3.x, accp->x))));
                accp->y = fmaf(a0, w0.y, fmaf(a1, w1.y, fmaf(a2, w2.y, fmaf(a3, w3.y, accp->y))));
                accp->z = fmaf(a0, w0.z, fmaf(a1, w1.z, fmaf(a2, w2.z, fmaf(a3, w3.z, accp->z))));
                accp->w = fmaf(a0, w0.w, fmaf(a1, w1.w, fmaf(a2, w2.w, fmaf(a3, w3.w, accp->w))));
            }
        }
        float4* xo = Xout + row * 32 + c4;
        xo[0] = acc0; xo[8] = acc1; xo[16] = acc2; xo[24] = acc3;
        if (hn) {
            float4* zo = Z4 + row * 32 + c4;
            float4 t;
            t.x = acc0.x * s; t.y = acc0.y * s; t.z = acc0.z * s; t.w = acc0.w * s; zo[0] = t;
            t.x = acc1.x * s; t.y = acc1.y * s; t.z = acc1.z * s; t.w = acc1.w * s; zo[8] = t;
            t.x = acc2.x * s; t.y = acc2.y * s; t.z = acc2.z * s; t.w = acc2.w * s; zo[16] = t;
            t.x = acc3.x * s; t.y = acc3.y * s; t.z = acc3.z * s; t.w = acc3.w * s; zo[24] = t;
        }
    }
}

// ---------------------------------------------------------------------------
extern "C" void kernel_launch(void* const* d_in, const int* in_sizes, int n_in,
                              void* d_out, int out_size) {
    const float* X = (const float*)d_in[0];
    const long long* ei = (const long long*)d_in[1];
    const float* eps = (const float*)d_in[2];
    const float* W1 = (const float*)d_in[3];
    const float* b1 = (const float*)d_in[4];
    const float* g1 = (const float*)d_in[5];
    const float* bt1 = (const float*)d_in[6];
    const float* W2 = (const float*)d_in[7];
    const float* b2 = (const float*)d_in[8];
    const float* g2 = (const float*)d_in[9];
    const float* bt2 = (const float*)d_in[10];
    const float* W3 = (const float*)d_in[11];
    const float* b3 = (const float*)d_in[12];

    const int GB = 592;   // GEMM grid
    const int SB = 2048;  // scatter grid

    k_detect<<<1, 32>>>(ei);
    k_init<<<4096, 256>>>((const float4*)X, eps);

    // xsel per layer: which buffer holds current X; osel: where gemm3 writes X_next
    int xsel[NL] = {0, 1, 2, 1};
    int osel[NL] = {1, 2, 1, 3};

    for (int l = 0; l < NL; l++) {
        k_scatter<<<SB, 256>>>((const float4*)X, ei, xsel[l]);
        k_gemm1<<<GB, 256>>>(W1 + l * HH * DD, b1 + l * HH);
        k_bn<<<1, 32>>>(1, g1 + l * HH, bt1 + l * HH);
        k_gemm2<<<GB, 256>>>(W2 + l * HH * HH, b2 + l * HH);
        k_bn<<<1, 32>>>(2, g2 + l * HH, bt2 + l * HH);
        int next_l = (l < NL - 1) ? (l + 1) : -1;
        k_gemm3<<<GB, 256>>>(W3 + l * DD * HH, b3 + l * DD,
                             (float4*)d_out, osel[l], eps, next_l);
    }
}

// round 8
// speedup vs baseline: 2.3246x; 2.0676x over previous
#include <cuda_runtime.h>

#define NN 100000
#define NE 1600000
#define DD 128
#define HH 32
#define NL 4

// ---- scratch (static device memory; no allocation) ----
__device__ __align__(16) float g_Z[NN * DD];   // aggregation output: (1+eps)X + sum(neighbors)
__device__ __align__(16) float g_XA[NN * DD];  // ping
__device__ __align__(16) float g_XB[NN * DD];  // pong
__device__ __align__(16) float g_Y1[NN * HH];
__device__ __align__(16) float g_Y2[NN * HH];
__device__ double g_stats1[2 * HH];
__device__ double g_stats2[2 * HH];
__device__ __align__(16) float g_bnA1[HH], g_bnC1[HH], g_bnA2[HH], g_bnC2[HH];
__device__ int g_ei64;
// CSR scratch
__device__ int g_deg[NN];
__device__ int g_off[NN + 1];
__device__ int g_cursor[NN];
__device__ int g_csr[NE];
__device__ int g_bsum[128];

// ---------------------------------------------------------------------------
__global__ void k_detect(const long long* __restrict__ ei) {
    if (threadIdx.x == 0 && blockIdx.x == 0) {
        int is64 = 1;
        for (int i = 0; i < 16; i++) {
            long long v = ei[i];
            if (v < 0 || v >= (long long)NN) { is64 = 0; break; }
        }
        g_ei64 = is64;
    }
}

// zero degree + stats
__global__ void k_prep() {
    int gid = blockIdx.x * blockDim.x + threadIdx.x;
    if (gid < NN) g_deg[gid] = 0;
    if (gid < 64) g_stats1[gid] = 0.0;
    else if (gid < 128) g_stats2[gid - 64] = 0.0;
}

__global__ void k_hist(const long long* __restrict__ ei) {
    int e = blockIdx.x * blockDim.x + threadIdx.x;
    if (e >= NE) return;
    int dst = g_ei64 ? (int)ei[NE + e] : ((const int*)ei)[NE + e];
    atomicAdd(&g_deg[dst], 1);
}

// block-wise inclusive scan (1024/block); block sums to g_bsum
__global__ void k_scanA() {
    __shared__ int s[1024];
    int gid = blockIdx.x * 1024 + threadIdx.x;
    int v = (gid < NN) ? g_deg[gid] : 0;
    s[threadIdx.x] = v;
    __syncthreads();
    for (int d = 1; d < 1024; d <<= 1) {
        int t = (threadIdx.x >= d) ? s[threadIdx.x - d] : 0;
        __syncthreads();
        s[threadIdx.x] += t;
        __syncthreads();
    }
    if (gid < NN) g_cursor[gid] = s[threadIdx.x];  // inclusive, temp in cursor
    if (threadIdx.x == 1023) g_bsum[blockIdx.x] = s[1023];
}

__global__ void k_scanB() {  // 1 block, 128 threads, scan 98 block sums
    __shared__ int s[128];
    int v = (threadIdx.x < 98) ? g_bsum[threadIdx.x] : 0;
    s[threadIdx.x] = v;
    __syncthreads();
    for (int d = 1; d < 128; d <<= 1) {
        int t = (threadIdx.x >= d) ? s[threadIdx.x - d] : 0;
        __syncthreads();
        s[threadIdx.x] += t;
        __syncthreads();
    }
    g_bsum[threadIdx.x] = s[threadIdx.x];  // inclusive
}

__global__ void k_scanC() {
    int gid = blockIdx.x * blockDim.x + threadIdx.x;
    if (gid >= NN) return;
    int b = gid >> 10;
    int excl = g_cursor[gid] - g_deg[gid] + (b ? g_bsum[b - 1] : 0);
    g_off[gid] = excl;
    g_cursor[gid] = excl;
    if (gid == 0) g_off[NN] = NE;
}

__global__ void k_fill(const long long* __restrict__ ei) {
    int e = blockIdx.x * blockDim.x + threadIdx.x;
    if (e >= NE) return;
    int src, dst;
    if (g_ei64) { src = (int)ei[e]; dst = (int)ei[NE + e]; }
    else { src = ((const int*)ei)[e]; dst = ((const int*)ei)[NE + e]; }
    int pos = atomicAdd(&g_cursor[dst], 1);
    g_csr[pos] = src;
}

// ---------------------------------------------------------------------------
// Aggregation (gather): Z[n] = (1+eps[l])*X[n] + sum_{s in N(n)} X[s]
// Warp per node; lane = float4 chunk.
// ---------------------------------------------------------------------------
__global__ void k_aggregate(const float4* __restrict__ Xin,
                            const float* __restrict__ eps, int l, int xsel) {
    const float4* X = (xsel == 0) ? Xin
                    : (xsel == 1) ? (const float4*)g_XA
                                  : (const float4*)g_XB;
    int gtid = blockIdx.x * blockDim.x + threadIdx.x;
    int wid = gtid >> 5;
    int lane = gtid & 31;
    if (wid >= NN) return;
    int beg = g_off[wid], end = g_off[wid + 1];
    float s = 1.0f + eps[l];
    float4 x = X[wid * 32 + lane];
    float4 acc;
    acc.x = x.x * s; acc.y = x.y * s; acc.z = x.z * s; acc.w = x.w * s;
    int e = beg;
    for (; e + 4 <= end; e += 4) {
        int s0 = g_csr[e], s1 = g_csr[e + 1], s2 = g_csr[e + 2], s3 = g_csr[e + 3];
        float4 v0 = X[s0 * 32 + lane];
        float4 v1 = X[s1 * 32 + lane];
        float4 v2 = X[s2 * 32 + lane];
        float4 v3 = X[s3 * 32 + lane];
        acc.x += (v0.x + v1.x) + (v2.x + v3.x);
        acc.y += (v0.y + v1.y) + (v2.y + v3.y);
        acc.z += (v0.z + v1.z) + (v2.z + v3.z);
        acc.w += (v0.w + v1.w) + (v2.w + v3.w);
    }
    for (; e < end; e++) {
        float4 v = X[g_csr[e] * 32 + lane];
        acc.x += v.x; acc.y += v.y; acc.z += v.z; acc.w += v.w;
    }
    ((float4*)g_Z)[wid * 32 + lane] = acc;
}

// ---------------------------------------------------------------------------
// GEMM1: Y1 = Z @ W1^T + b1 (K=128 -> 32) + column stats.
// Warp = 16 rows; thread (rr=lane>>3, c4=lane&7) = 4 rows x 4 cols.
// ---------------------------------------------------------------------------
__global__ __launch_bounds__(256) void k_gemm1(const float* __restrict__ W1l,
                                               const float* __restrict__ b1l) {
    __shared__ __align__(16) float Ws[DD * HH];  // Ws[k*32+c] = W1l[c*128+k]
    __shared__ float bsum[HH], bsq[HH];
    for (int i = threadIdx.x; i < DD * HH; i += 256) {
        int k = i >> 5, c = i & 31;
        Ws[k * 32 + c] = W1l[c * DD + k];
    }
    if (threadIdx.x < HH) { bsum[threadIdx.x] = 0.f; bsq[threadIdx.x] = 0.f; }
    __syncthreads();
    const float4* Ws4 = (const float4*)Ws;
    int lane = threadIdx.x & 31;
    int rr = lane >> 3, c4 = lane & 7, base = lane & 24;
    int gw = blockIdx.x * 8 + (threadIdx.x >> 5);
    int nw = gridDim.x * 8;
    const float4* Z4 = (const float4*)g_Z;
    float4 bias = ((const float4*)b1l)[c4];
    float4 ls = {0, 0, 0, 0}, lq = {0, 0, 0, 0};
    for (int rb = gw * 16; rb < NN; rb += nw * 16) {
        int row0 = rb + 4 * rr;
        float4 z[4][4];
#pragma unroll
        for (int i = 0; i < 4; i++)
#pragma unroll
            for (int m = 0; m < 4; m++)
                z[i][m] = Z4[(row0 + i) * 32 + c4 + 8 * m];
        float4 acc[4] = {bias, bias, bias, bias};
#pragma unroll
        for (int m = 0; m < 4; m++) {
#pragma unroll 4
            for (int kc2 = 0; kc2 < 8; kc2++) {
                int srcl = base | kc2;
                int kk = (m * 8 + kc2) * 4;
                float4 w0 = Ws4[(kk + 0) * 8 + c4];
                float4 w1 = Ws4[(kk + 1) * 8 + c4];
                float4 w2 = Ws4[(kk + 2) * 8 + c4];
                float4 w3 = Ws4[(kk + 3) * 8 + c4];
#pragma unroll
                for (int i = 0; i < 4; i++) {
                    float a0 = __shfl_sync(0xffffffffu, z[i][m].x, srcl);
                    float a1 = __shfl_sync(0xffffffffu, z[i][m].y, srcl);
                    float a2 = __shfl_sync(0xffffffffu, z[i][m].z, srcl);
                    float a3 = __shfl_sync(0xffffffffu, z[i][m].w, srcl);
                    acc[i].x = fmaf(a0, w0.x, fmaf(a1, w1.x, fmaf(a2, w2.x, fmaf(a3, w3.x, acc[i].x))));
                    acc[i].y = fmaf(a0, w0.y, fmaf(a1, w1.y, fmaf(a2, w2.y, fmaf(a3, w3.y, acc[i].y))));
                    acc[i].z = fmaf(a0, w0.z, fmaf(a1, w1.z, fmaf(a2, w2.z, fmaf(a3, w3.z, acc[i].z))));
                    acc[i].w = fmaf(a0, w0.w, fmaf(a1, w1.w, fmaf(a2, w2.w, fmaf(a3, w3.w, acc[i].w))));
                }
            }
        }
#pragma unroll
        for (int i = 0; i < 4; i++) {
            ((float4*)g_Y1)[(row0 + i) * 8 + c4] = acc[i];
            ls.x += acc[i].x; ls.y += acc[i].y; ls.z += acc[i].z; ls.w += acc[i].w;
            lq.x = fmaf(acc[i].x, acc[i].x, lq.x); lq.y = fmaf(acc[i].y, acc[i].y, lq.y);
            lq.z = fmaf(acc[i].z, acc[i].z, lq.z); lq.w = fmaf(acc[i].w, acc[i].w, lq.w);
        }
    }
    atomicAdd(&bsum[4 * c4 + 0], ls.x); atomicAdd(&bsum[4 * c4 + 1], ls.y);
    atomicAdd(&bsum[4 * c4 + 2], ls.z); atomicAdd(&bsum[4 * c4 + 3], ls.w);
    atomicAdd(&bsq[4 * c4 + 0], lq.x);  atomicAdd(&bsq[4 * c4 + 1], lq.y);
    atomicAdd(&bsq[4 * c4 + 2], lq.z);  atomicAdd(&bsq[4 * c4 + 3], lq.w);
    __syncthreads();
    if (threadIdx.x < HH) {
        atomicAdd(&g_stats1[threadIdx.x], (double)bsum[threadIdx.x]);
        atomicAdd(&g_stats1[HH + threadIdx.x], (double)bsq[threadIdx.x]);
    }
}

// ---------------------------------------------------------------------------
__global__ void k_bn(int which, const float* __restrict__ g,
                     const float* __restrict__ bt) {
    int c = threadIdx.x;
    if (c >= HH) return;
    const double* st = (which == 1) ? g_stats1 : g_stats2;
    float* A = (which == 1) ? g_bnA1 : g_bnA2;
    float* C = (which == 1) ? g_bnC1 : g_bnC2;
    double* zs = (which == 1) ? g_stats2 : g_stats1;
    double mean = st[c] / (double)NN;
    double var = st[HH + c] / (double)NN - mean * mean;
    float a = g[c] * rsqrtf((float)var + 1e-5f);
    A[c] = a;
    C[c] = bt[c] - a * (float)mean;
    zs[c] = 0.0;
    zs[HH + c] = 0.0;
}

// ---------------------------------------------------------------------------
// GEMM2: h = relu(bn1(Y1)); Y2 = h @ W2^T + b2 (32 -> 32) + stats2.
// Warp = 16 rows; thread = 4 rows x 4 cols.
// ---------------------------------------------------------------------------
__global__ __launch_bounds__(256) void k_gemm2(const float* __restrict__ W2l,
                                               const float* __restrict__ b2l) {
    __shared__ __align__(16) float Ws[HH * HH];
    __shared__ float bsum[HH], bsq[HH];
    for (int i = threadIdx.x; i < HH * HH; i += 256) {
        int k = i >> 5, c = i & 31;
        Ws[k * 32 + c] = W2l[c * HH + k];
    }
    if (threadIdx.x < HH) { bsum[threadIdx.x] = 0.f; bsq[threadIdx.x] = 0.f; }
    __syncthreads();
    const float4* Ws4 = (const float4*)Ws;
    int lane = threadIdx.x & 31;
    int rr = lane >> 3, c4 = lane & 7, base = lane & 24;
    int gw = blockIdx.x * 8 + (threadIdx.x >> 5);
    int nw = gridDim.x * 8;
    float4 bias = ((const float4*)b2l)[c4];
    float4 ba = ((const float4*)g_bnA1)[c4];
    float4 bc = ((const float4*)g_bnC1)[c4];
    float4 ls = {0, 0, 0, 0}, lq = {0, 0, 0, 0};
    for (int rb = gw * 16; rb < NN; rb += nw * 16) {
        int row0 = rb + 4 * rr;
        float4 h[4];
#pragma unroll
        for (int i = 0; i < 4; i++) {
            float4 y = ((const float4*)g_Y1)[(row0 + i) * 8 + c4];
            h[i].x = fmaxf(fmaf(ba.x, y.x, bc.x), 0.f);
            h[i].y = fmaxf(fmaf(ba.y, y.y, bc.y), 0.f);
            h[i].z = fmaxf(fmaf(ba.z, y.z, bc.z), 0.f);
            h[i].w = fmaxf(fmaf(ba.w, y.w, bc.w), 0.f);
        }
        float4 acc[4] = {bias, bias, bias, bias};
#pragma unroll 4
        for (int kc2 = 0; kc2 < 8; kc2++) {
            int srcl = base | kc2;
            int kk = kc2 * 4;
            float4 w0 = Ws4[(kk + 0) * 8 + c4];
            float4 w1 = Ws4[(kk + 1) * 8 + c4];
            float4 w2 = Ws4[(kk + 2) * 8 + c4];
            float4 w3 = Ws4[(kk + 3) * 8 + c4];
#pragma unroll
            for (int i = 0; i < 4; i++) {
                float a0 = __shfl_sync(0xffffffffu, h[i].x, srcl);
                float a1 = __shfl_sync(0xffffffffu, h[i].y, srcl);
                float a2 = __shfl_sync(0xffffffffu, h[i].z, srcl);
                float a3 = __shfl_sync(0xffffffffu, h[i].w, srcl);
                acc[i].x = fmaf(a0, w0.x, fmaf(a1, w1.x, fmaf(a2, w2.x, fmaf(a3, w3.x, acc[i].x))));
                acc[i].y = fmaf(a0, w0.y, fmaf(a1, w1.y, fmaf(a2, w2.y, fmaf(a3, w3.y, acc[i].y))));
                acc[i].z = fmaf(a0, w0.z, fmaf(a1, w1.z, fmaf(a2, w2.z, fmaf(a3, w3.z, acc[i].z))));
                acc[i].w = fmaf(a0, w0.w, fmaf(a1, w1.w, fmaf(a2, w2.w, fmaf(a3, w3.w, acc[i].w))));
            }
        }
#pragma unroll
        for (int i = 0; i < 4; i++) {
            ((float4*)g_Y2)[(row0 + i) * 8 + c4] = acc[i];
            ls.x += acc[i].x; ls.y += acc[i].y; ls.z += acc[i].z; ls.w += acc[i].w;
            lq.x = fmaf(acc[i].x, acc[i].x, lq.x); lq.y = fmaf(acc[i].y, acc[i].y, lq.y);
            lq.z = fmaf(acc[i].z, acc[i].z, lq.z); lq.w = fmaf(acc[i].w, acc[i].w, lq.w);
        }
    }
    atomicAdd(&bsum[4 * c4 + 0], ls.x); atomicAdd(&bsum[4 * c4 + 1], ls.y);
    atomicAdd(&bsum[4 * c4 + 2], ls.z); atomicAdd(&bsum[4 * c4 + 3], ls.w);
    atomicAdd(&bsq[4 * c4 + 0], lq.x);  atomicAdd(&bsq[4 * c4 + 1], lq.y);
    atomicAdd(&bsq[4 * c4 + 2], lq.z);  atomicAdd(&bsq[4 * c4 + 3], lq.w);
    __syncthreads();
    if (threadIdx.x < HH) {
        atomicAdd(&g_stats2[threadIdx.x], (double)bsum[threadIdx.x]);
        atomicAdd(&g_stats2[HH + threadIdx.x], (double)bsq[threadIdx.x]);
    }
}

// ---------------------------------------------------------------------------
// GEMM3: h = relu(bn2(Y2)); X_next = h @ W3^T + b3 (32 -> 128)
// Warp = 16 rows; thread = 4 rows x 16 cols (4 chunks).
// ---------------------------------------------------------------------------
__global__ __launch_bounds__(256) void k_gemm3(const float* __restrict__ W3l,
                                               const float* __restrict__ b3l,
                                               float4* __restrict__ Xext, int osel) {
    __shared__ __align__(16) float Wt[HH * DD];  // Wt[k*128+c] = W3l[c*32+k]
    for (int i = threadIdx.x; i < HH * DD; i += 256) {
        int c = i >> 5, k = i & 31;
        Wt[k * DD + c] = W3l[i];
    }
    __syncthreads();
    const float4* Wt4 = (const float4*)Wt;
    float4* Xout = (osel == 1) ? (float4*)g_XA
                 : (osel == 2) ? (float4*)g_XB
                               : Xext;
    int lane = threadIdx.x & 31;
    int rr = lane >> 3, c4 = lane & 7, base = lane & 24;
    int gw = blockIdx.x * 8 + (threadIdx.x >> 5);
    int nw = gridDim.x * 8;
    float4 ba = ((const float4*)g_bnA2)[c4];
    float4 bc = ((const float4*)g_bnC2)[c4];
    float4 bias[4];
#pragma unroll
    for (int u = 0; u < 4; u++) bias[u] = ((const float4*)b3l)[c4 + 8 * u];
    for (int rb = gw * 16; rb < NN; rb += nw * 16) {
        int row0 = rb + 4 * rr;
        float4 h[4];
#pragma unroll
        for (int i = 0; i < 4; i++) {
            float4 y = ((const float4*)g_Y2)[(row0 + i) * 8 + c4];
            h[i].x = fmaxf(fmaf(ba.x, y.x, bc.x), 0.f);
            h[i].y = fmaxf(fmaf(ba.y, y.y, bc.y), 0.f);
            h[i].z = fmaxf(fmaf(ba.z, y.z, bc.z), 0.f);
            h[i].w = fmaxf(fmaf(ba.w, y.w, bc.w), 0.f);
        }
        float4 acc[4][4];
#pragma unroll
        for (int i = 0; i < 4; i++)
#pragma unroll
            for (int u = 0; u < 4; u++) acc[i][u] = bias[u];
        for (int kc2 = 0; kc2 < 8; kc2++) {
            int srcl = base | kc2;
            int kk = kc2 * 4;
#pragma unroll
            for (int i = 0; i < 4; i++) {
                float a0 = __shfl_sync(0xffffffffu, h[i].x, srcl);
                float a1 = __shfl_sync(0xffffffffu, h[i].y, srcl);
                float a2 = __shfl_sync(0xffffffffu, h[i].z, srcl);
                float a3 = __shfl_sync(0xffffffffu, h[i].w, srcl);
#pragma unroll
                for (int u = 0; u < 4; u++) {
                    float4 w0 = Wt4[(kk + 0) * 32 + c4 + 8 * u];
                    float4 w1 = Wt4[(kk + 1) * 32 + c4 + 8 * u];
                    float4 w2 = Wt4[(kk + 2) * 32 + c4 + 8 * u];
                    float4 w3 = Wt4[(kk + 3) * 32 + c4 + 8 * u];
                    acc[i][u].x = fmaf(a0, w0.x, fmaf(a1, w1.x, fmaf(a2, w2.x, fmaf(a3, w3.x, acc[i][u].x))));
                    acc[i][u].y = fmaf(a0, w0.y, fmaf(a1, w1.y, fmaf(a2, w2.y, fmaf(a3, w3.y, acc[i][u].y))));
                    acc[i][u].z = fmaf(a0, w0.z, fmaf(a1, w1.z, fmaf(a2, w2.z, fmaf(a3, w3.z, acc[i][u].z))));
                    acc[i][u].w = fmaf(a0, w0.w, fmaf(a1, w1.w, fmaf(a2, w2.w, fmaf(a3, w3.w, acc[i][u].w))));
                }
            }
        }
#pragma unroll
        for (int i = 0; i < 4; i++) {
            float4* xo = Xout + (row0 + i) * 32 + c4;
            xo[0] = acc[i][0]; xo[8] = acc[i][1]; xo[16] = acc[i][2]; xo[24] = acc[i][3];
        }
    }
}

// ---------------------------------------------------------------------------
extern "C" void kernel_launch(void* const* d_in, const int* in_sizes, int n_in,
                              void* d_out, int out_size) {
    const float* X = (const float*)d_in[0];
    const long long* ei = (const long long*)d_in[1];
    const float* eps = (const float*)d_in[2];
    const float* W1 = (const float*)d_in[3];
    const float* b1 = (const float*)d_in[4];
    const float* g1 = (const float*)d_in[5];
    const float* bt1 = (const float*)d_in[6];
    const float* W2 = (const float*)d_in[7];
    const float* b2 = (const float*)d_in[8];
    const float* g2 = (const float*)d_in[9];
    const float* bt2 = (const float*)d_in[10];
    const float* W3 = (const float*)d_in[11];
    const float* b3 = (const float*)d_in[12];

    const int GB = 296;  // GEMM grid (2 blocks/SM)

    k_detect<<<1, 32>>>(ei);
    k_prep<<<392, 256>>>();
    k_hist<<<6250, 256>>>(ei);
    k_scanA<<<98, 1024>>>();
    k_scanB<<<1, 128>>>();
    k_scanC<<<392, 256>>>();
    k_fill<<<6250, 256>>>(ei);

    int xsel[NL] = {0, 1, 2, 1};
    int osel[NL] = {1, 2, 1, 3};

    for (int l = 0; l < NL; l++) {
        k_aggregate<<<12500, 256>>>((const float4*)X, eps, l, xsel[l]);
        k_gemm1<<<GB, 256>>>(W1 + l * HH * DD, b1 + l * HH);
        k_bn<<<1, 32>>>(1, g1 + l * HH, bt1 + l * HH);
        k_gemm2<<<GB, 256>>>(W2 + l * HH * HH, b2 + l * HH);
        k_bn<<<1, 32>>>(2, g2 + l * HH, bt2 + l * HH);
        k_gemm3<<<GB, 256>>>(W3 + l * DD * HH, b3 + l * DD,
                             (float4*)d_out, osel[l]);
    }
}

// round 11
// speedup vs baseline: 3.6695x; 1.5785x over previous
#include <cuda_runtime.h>

#define NN 100000
#define NE 1600000
#define DD 128
#define HH 32
#define NL 4

// ---- scratch (static device memory; no allocation) ----
__device__ __align__(16) float g_U[NN * HH];   // projected features (32-dim)
__device__ __align__(16) float g_Y1[NN * HH];
__device__ __align__(16) float g_Y2[NN * HH];
__device__ __align__(16) float g_Wc[3 * HH * HH];  // composed W1_{l+1}@W3_l, layout [k*32+c]
__device__ __align__(16) float g_bc[3 * HH];       // composed bias W1_{l+1}@b3_t
__device__ double g_stats1[2 * HH];
__device__ double g_stats2[2 * HH];
__device__ __align__(16) float g_bnA1[HH], g_bnC1[HH], g_bnA2[HH], g_bnC2[HH];
__device__ int g_ei64;
// CSR scratch
__device__ int g_deg[NN];
__device__ int g_off[NN + 1];
__device__ int g_cursor[NN];
__device__ int g_csr[NE];
__device__ int g_bsum[128];

// ---------------------------------------------------------------------------
__global__ void k_detect(const long long* __restrict__ ei) {
    if (threadIdx.x == 0 && blockIdx.x == 0) {
        int is64 = 1;
        for (int i = 0; i < 16; i++) {
            long long v = ei[i];
            if (v < 0 || v >= (long long)NN) { is64 = 0; break; }
        }
        g_ei64 = is64;
    }
}

__global__ void k_prep() {
    int gid = blockIdx.x * blockDim.x + threadIdx.x;
    if (gid < NN) g_deg[gid] = 0;
    if (gid < 64) g_stats1[gid] = 0.0;
    else if (gid < 128) g_stats2[gid - 64] = 0.0;
}

__global__ void k_hist(const long long* __restrict__ ei) {
    int e = blockIdx.x * blockDim.x + threadIdx.x;
    if (e >= NE) return;
    int dst = g_ei64 ? (int)ei[NE + e] : ((const int*)ei)[NE + e];
    atomicAdd(&g_deg[dst], 1);
}

__global__ void k_scanA() {
    __shared__ int s[1024];
    int gid = blockIdx.x * 1024 + threadIdx.x;
    int v = (gid < NN) ? g_deg[gid] : 0;
    s[threadIdx.x] = v;
    __syncthreads();
    for (int d = 1; d < 1024; d <<= 1) {
        int t = (threadIdx.x >= d) ? s[threadIdx.x - d] : 0;
        __syncthreads();
        s[threadIdx.x] += t;
        __syncthreads();
    }
    if (gid < NN) g_cursor[gid] = s[threadIdx.x];
    if (threadIdx.x == 1023) g_bsum[blockIdx.x] = s[1023];
}

__global__ void k_scanB() {
    __shared__ int s[128];
    int v = (threadIdx.x < 98) ? g_bsum[threadIdx.x] : 0;
    s[threadIdx.x] = v;
    __syncthreads();
    for (int d = 1; d < 128; d <<= 1) {
        int t = (threadIdx.x >= d) ? s[threadIdx.x - d] : 0;
        __syncthreads();
        s[threadIdx.x] += t;
        __syncthreads();
    }
    g_bsum[threadIdx.x] = s[threadIdx.x];
}

__global__ void k_scanC() {
    int gid = blockIdx.x * blockDim.x + threadIdx.x;
    if (gid >= NN) return;
    int b = gid >> 10;
    int excl = g_cursor[gid] - g_deg[gid] + (b ? g_bsum[b - 1] : 0);
    g_off[gid] = excl;
    g_cursor[gid] = excl;
    if (gid == 0) g_off[NN] = NE;
}

__global__ void k_fill(const long long* __restrict__ ei) {
    int e = blockIdx.x * blockDim.x + threadIdx.x;
    if (e >= NE) return;
    int src, dst;
    if (g_ei64) { src = (int)ei[e]; dst = (int)ei[NE + e]; }
    else { src = ((const int*)ei)[e]; dst = ((const int*)ei)[NE + e]; }
    int pos = atomicAdd(&g_cursor[dst], 1);
    g_csr[pos] = src;
}

// ---------------------------------------------------------------------------
// Compose Wc_t = W1_{t+1} @ W3_t (stored transposed [k*32+c]), bc_t = W1_{t+1} @ b3_t
// ---------------------------------------------------------------------------
__global__ void k_compose(const float* __restrict__ W1, const float* __restrict__ W3,
                          const float* __restrict__ b3) {
    int t = blockIdx.x;
    int tid = threadIdx.x;
    int c = tid >> 5, k = tid & 31;
    const float* w1 = W1 + (t + 1) * HH * DD + c * DD;
    const float* w3 = W3 + t * DD * HH;
    float acc = 0.f;
#pragma unroll 8
    for (int d = 0; d < DD; d++) acc = fmaf(w1[d], w3[d * HH + k], acc);
    g_Wc[t * HH * HH + k * HH + c] = acc;
    if (tid < HH) {
        const float* w1c = W1 + (t + 1) * HH * DD + tid * DD;
        const float* b3t = b3 + t * DD;
        float a = 0.f;
        for (int d = 0; d < DD; d++) a = fmaf(w1c[d], b3t[d], a);
        g_bc[t * HH + tid] = a;
    }
}

// ---------------------------------------------------------------------------
// GEMM1: U = X_in @ W1_0^T  (128 -> 32), no bias, no stats.
// ---------------------------------------------------------------------------
__global__ __launch_bounds__(256) void k_gemm1(const float4* __restrict__ Xin,
                                               const float* __restrict__ W1l) {
    __shared__ __align__(16) float Ws[DD * HH];  // Ws[k*32+c] = W1l[c*128+k]
    for (int i = threadIdx.x; i < DD * HH; i += 256) {
        int k = i >> 5, c = i & 31;
        Ws[k * 32 + c] = W1l[c * DD + k];
    }
    __syncthreads();
    const float4* Ws4 = (const float4*)Ws;
    int lane = threadIdx.x & 31;
    int rr = lane >> 3, c4 = lane & 7, base = lane & 24;
    int gw = blockIdx.x * 8 + (threadIdx.x >> 5);
    int nw = gridDim.x * 8;
    for (int rb = gw * 16; rb < NN; rb += nw * 16) {
        int row0 = rb + 4 * rr;
        float4 z[4][4];
#pragma unroll
        for (int i = 0; i < 4; i++)
#pragma unroll
            for (int m = 0; m < 4; m++)
                z[i][m] = Xin[(row0 + i) * 32 + c4 + 8 * m];
        float4 acc[4] = {{0,0,0,0},{0,0,0,0},{0,0,0,0},{0,0,0,0}};
#pragma unroll
        for (int m = 0; m < 4; m++) {
#pragma unroll 4
            for (int kc2 = 0; kc2 < 8; kc2++) {
                int srcl = base | kc2;
                int kk = (m * 8 + kc2) * 4;
                float4 w0 = Ws4[(kk + 0) * 8 + c4];
                float4 w1 = Ws4[(kk + 1) * 8 + c4];
                float4 w2 = Ws4[(kk + 2) * 8 + c4];
                float4 w3 = Ws4[(kk + 3) * 8 + c4];
#pragma unroll
                for (int i = 0; i < 4; i++) {
                    float a0 = __shfl_sync(0xffffffffu, z[i][m].x, srcl);
                    float a1 = __shfl_sync(0xffffffffu, z[i][m].y, srcl);
                    float a2 = __shfl_sync(0xffffffffu, z[i][m].z, srcl);
                    float a3 = __shfl_sync(0xffffffffu, z[i][m].w, srcl);
                    acc[i].x = fmaf(a0, w0.x, fmaf(a1, w1.x, fmaf(a2, w2.x, fmaf(a3, w3.x, acc[i].x))));
                    acc[i].y = fmaf(a0, w0.y, fmaf(a1, w1.y, fmaf(a2, w2.y, fmaf(a3, w3.y, acc[i].y))));
                    acc[i].z = fmaf(a0, w0.z, fmaf(a1, w1.z, fmaf(a2, w2.z, fmaf(a3, w3.z, acc[i].z))));
                    acc[i].w = fmaf(a0, w0.w, fmaf(a1, w1.w, fmaf(a2, w2.w, fmaf(a3, w3.w, acc[i].w))));
                }
            }
        }
#pragma unroll
        for (int i = 0; i < 4; i++)
            ((float4*)g_U)[(row0 + i) * 8 + c4] = acc[i];
    }
}

// ---------------------------------------------------------------------------
// 32-dim aggregation: Y1[n] = (1+eps_l)*U[n] + sum_{s in N(n)} U[s] + b1
// Warp per node; lane = column. Accumulates stats1.
// ---------------------------------------------------------------------------
__global__ __launch_bounds__(256) void k_agg32(const float* __restrict__ eps, int l,
                                               const float* __restrict__ b1l) {
    __shared__ float ssum[8][HH], ssq[8][HH];
    int warp = threadIdx.x >> 5, lane = threadIdx.x & 31;
    int gw = blockIdx.x * 8 + warp;
    int nw = gridDim.x * 8;
    float s = 1.0f + eps[l];
    float bias = b1l[lane];
    float lsum = 0.f, lsq = 0.f;
    for (int n = gw; n < NN; n += nw) {
        int beg = g_off[n], end = g_off[n + 1];
        float acc = fmaf(s, g_U[n * HH + lane], bias);
        int e = beg;
        for (; e + 4 <= end; e += 4) {
            int s0 = g_csr[e], s1 = g_csr[e + 1], s2 = g_csr[e + 2], s3 = g_csr[e + 3];
            float v0 = g_U[s0 * HH + lane];
            float v1 = g_U[s1 * HH + lane];
            float v2 = g_U[s2 * HH + lane];
            float v3 = g_U[s3 * HH + lane];
            acc += (v0 + v1) + (v2 + v3);
        }
        for (; e < end; e++) acc += g_U[g_csr[e] * HH + lane];
        g_Y1[n * HH + lane] = acc;
        lsum += acc;
        lsq = fmaf(acc, acc, lsq);
    }
    ssum[warp][lane] = lsum;
    ssq[warp][lane] = lsq;
    __syncthreads();
    if (threadIdx.x < HH) {
        float a = 0.f, q = 0.f;
        for (int w = 0; w < 8; w++) { a += ssum[w][threadIdx.x]; q += ssq[w][threadIdx.x]; }
        atomicAdd(&g_stats1[threadIdx.x], (double)a);
        atomicAdd(&g_stats1[HH + threadIdx.x], (double)q);
    }
}

// ---------------------------------------------------------------------------
__global__ void k_bn(int which, const float* __restrict__ g,
                     const float* __restrict__ bt) {
    int c = threadIdx.x;
    if (c >= HH) return;
    const double* st = (which == 1) ? g_stats1 : g_stats2;
    float* A = (which == 1) ? g_bnA1 : g_bnA2;
    float* C = (which == 1) ? g_bnC1 : g_bnC2;
    double* zs = (which == 1) ? g_stats2 : g_stats1;
    double mean = st[c] / (double)NN;
    double var = st[HH + c] / (double)NN - mean * mean;
    float a = g[c] * rsqrtf((float)var + 1e-5f);
    A[c] = a;
    C[c] = bt[c] - a * (float)mean;
    zs[c] = 0.0;
    zs[HH + c] = 0.0;
}

// ---------------------------------------------------------------------------
// Generic 32->32: out = relu(bn(in)) @ W^T + bias. Optional stats2 accumulate.
// io: 0 -> in=g_Y1, out=g_Y2 ; 1 -> in=g_Y2, out=g_U   (resolved in DEVICE code!)
// trans >= 0: weight = g_Wc[trans] (pre-transposed), bias = g_bc[trans].
// trans <  0: weight = W2l (transposed on load), bias = b2l.
// bnsel: 1 -> bnA1/C1, 2 -> bnA2/C2.
// ---------------------------------------------------------------------------
__global__ __launch_bounds__(256) void k_gemm32(int io,
                                                const float* __restrict__ W2l,
                                                const float* __restrict__ b2l,
                                                int trans, int do_stats, int bnsel) {
    __shared__ __align__(16) float Ws[HH * HH];
    __shared__ float bsum[HH], bsq[HH];
    const float4* in = (io == 0) ? (const float4*)g_Y1 : (const float4*)g_Y2;
    float4* out = (io == 0) ? (float4*)g_Y2 : (float4*)g_U;
    if (trans >= 0) {
        for (int i = threadIdx.x; i < HH * HH; i += 256)
            Ws[i] = g_Wc[trans * HH * HH + i];
    } else {
        for (int i = threadIdx.x; i < HH * HH; i += 256) {
            int k = i >> 5, c = i & 31;
            Ws[k * 32 + c] = W2l[c * HH + k];
        }
    }
    if (threadIdx.x < HH) { bsum[threadIdx.x] = 0.f; bsq[threadIdx.x] = 0.f; }
    __syncthreads();
    const float4* Ws4 = (const float4*)Ws;
    int lane = threadIdx.x & 31;
    int rr = lane >> 3, c4 = lane & 7, base = lane & 24;
    int gw = blockIdx.x * 8 + (threadIdx.x >> 5);
    int nw = gridDim.x * 8;
    float4 bias = (trans >= 0) ? ((const float4*)(g_bc + trans * HH))[c4]
                               : ((const float4*)b2l)[c4];
    const float* An = (bnsel == 1) ? g_bnA1 : g_bnA2;
    const float* Cn = (bnsel == 1) ? g_bnC1 : g_bnC2;
    float4 ba = ((const float4*)An)[c4];
    float4 bc = ((const float4*)Cn)[c4];
    float4 ls = {0, 0, 0, 0}, lq = {0, 0, 0, 0};
    for (int rb = gw * 16; rb < NN; rb += nw * 16) {
        int row0 = rb + 4 * rr;
        float4 h[4];
#pragma unroll
        for (int i = 0; i < 4; i++) {
            float4 y = in[(row0 + i) * 8 + c4];
            h[i].x = fmaxf(fmaf(ba.x, y.x, bc.x), 0.f);
            h[i].y = fmaxf(fmaf(ba.y, y.y, bc.y), 0.f);
            h[i].z = fmaxf(fmaf(ba.z, y.z, bc.z), 0.f);
            h[i].w = fmaxf(fmaf(ba.w, y.w, bc.w), 0.f);
        }
        float4 acc[4] = {bias, bias, bias, bias};
#pragma unroll 4
        for (int kc2 = 0; kc2 < 8; kc2++) {
            int srcl = base | kc2;
            int kk = kc2 * 4;
            float4 w0 = Ws4[(kk + 0) * 8 + c4];
            float4 w1 = Ws4[(kk + 1) * 8 + c4];
            float4 w2 = Ws4[(kk + 2) * 8 + c4];
            float4 w3 = Ws4[(kk + 3) * 8 + c4];
#pragma unroll
            for (int i = 0; i < 4; i++) {
                float a0 = __shfl_sync(0xffffffffu, h[i].x, srcl);
                float a1 = __shfl_sync(0xffffffffu, h[i].y, srcl);
                float a2 = __shfl_sync(0xffffffffu, h[i].z, srcl);
                float a3 = __shfl_sync(0xffffffffu, h[i].w, srcl);
                acc[i].x = fmaf(a0, w0.x, fmaf(a1, w1.x, fmaf(a2, w2.x, fmaf(a3, w3.x, acc[i].x))));
                acc[i].y = fmaf(a0, w0.y, fmaf(a1, w1.y, fmaf(a2, w2.y, fmaf(a3, w3.y, acc[i].y))));
                acc[i].z = fmaf(a0, w0.z, fmaf(a1, w1.z, fmaf(a2, w2.z, fmaf(a3, w3.z, acc[i].z))));
                acc[i].w = fmaf(a0, w0.w, fmaf(a1, w1.w, fmaf(a2, w2.w, fmaf(a3, w3.w, acc[i].w))));
            }
        }
#pragma unroll
        for (int i = 0; i < 4; i++) {
            out[(row0 + i) * 8 + c4] = acc[i];
            if (do_stats) {
                ls.x += acc[i].x; ls.y += acc[i].y; ls.z += acc[i].z; ls.w += acc[i].w;
                lq.x = fmaf(acc[i].x, acc[i].x, lq.x); lq.y = fmaf(acc[i].y, acc[i].y, lq.y);
                lq.z = fmaf(acc[i].z, acc[i].z, lq.z); lq.w = fmaf(acc[i].w, acc[i].w, lq.w);
            }
        }
    }
    if (do_stats) {
        atomicAdd(&bsum[4 * c4 + 0], ls.x); atomicAdd(&bsum[4 * c4 + 1], ls.y);
        atomicAdd(&bsum[4 * c4 + 2], ls.z); atomicAdd(&bsum[4 * c4 + 3], ls.w);
        atomicAdd(&bsq[4 * c4 + 0], lq.x);  atomicAdd(&bsq[4 * c4 + 1], lq.y);
        atomicAdd(&bsq[4 * c4 + 2], lq.z);  atomicAdd(&bsq[4 * c4 + 3], lq.w);
        __syncthreads();
        if (threadIdx.x < HH) {
            atomicAdd(&g_stats2[threadIdx.x], (double)bsum[threadIdx.x]);
            atomicAdd(&g_stats2[HH + threadIdx.x], (double)bsq[threadIdx.x]);
        }
    }
}

// ---------------------------------------------------------------------------
// Final GEMM3: out = relu(bn2(Y2)) @ W3^T + b3  (32 -> 128), write d_out.
// ---------------------------------------------------------------------------
__global__ __launch_bounds__(256) void k_gemm3(const float* __restrict__ W3l,
                                               const float* __restrict__ b3l,
                                               float4* __restrict__ Xout) {
    __shared__ __align__(16) float Wt[HH * DD];  // Wt[k*128+c] = W3l[c*32+k]
    for (int i = threadIdx.x; i < HH * DD; i += 256) {
        int c = i >> 5, k = i & 31;
        Wt[k * DD + c] = W3l[i];
    }
    __syncthreads();
    const float4* Wt4 = (const float4*)Wt;
    int lane = threadIdx.x & 31;
    int rr = lane >> 3, c4 = lane & 7, base = lane & 24;
    int gw = blockIdx.x * 8 + (threadIdx.x >> 5);
    int nw = gridDim.x * 8;
    float4 ba = ((const float4*)g_bnA2)[c4];
    float4 bc = ((const float4*)g_bnC2)[c4];
    float4 bias[4];
#pragma unroll
    for (int u = 0; u < 4; u++) bias[u] = ((const float4*)b3l)[c4 + 8 * u];
    for (int rb = gw * 16; rb < NN; rb += nw * 16) {
        int row0 = rb + 4 * rr;
        float4 h[4];
#pragma unroll
        for (int i = 0; i < 4; i++) {
            float4 y = ((const float4*)g_Y2)[(row0 + i) * 8 + c4];
            h[i].x = fmaxf(fmaf(ba.x, y.x, bc.x), 0.f);
            h[i].y = fmaxf(fmaf(ba.y, y.y, bc.y), 0.f);
            h[i].z = fmaxf(fmaf(ba.z, y.z, bc.z), 0.f);
            h[i].w = fmaxf(fmaf(ba.w, y.w, bc.w), 0.f);
        }
        float4 acc[4][4];
#pragma unroll
        for (int i = 0; i < 4; i++)
#pragma unroll
            for (int u = 0; u < 4; u++) acc[i][u] = bias[u];
        for (int kc2 = 0; kc2 < 8; kc2++) {
            int srcl = base | kc2;
            int kk = kc2 * 4;
#pragma unroll
            for (int i = 0; i < 4; i++) {
                float a0 = __shfl_sync(0xffffffffu, h[i].x, srcl);
                float a1 = __shfl_sync(0xffffffffu, h[i].y, srcl);
                float a2 = __shfl_sync(0xffffffffu, h[i].z, srcl);
                float a3 = __shfl_sync(0xffffffffu, h[i].w, srcl);
#pragma unroll
                for (int u = 0; u < 4; u++) {
                    float4 w0 = Wt4[(kk + 0) * 32 + c4 + 8 * u];
                    float4 w1 = Wt4[(kk + 1) * 32 + c4 + 8 * u];
                    float4 w2 = Wt4[(kk + 2) * 32 + c4 + 8 * u];
                    float4 w3 = Wt4[(kk + 3) * 32 + c4 + 8 * u];
                    acc[i][u].x = fmaf(a0, w0.x, fmaf(a1, w1.x, fmaf(a2, w2.x, fmaf(a3, w3.x, acc[i][u].x))));
                    acc[i][u].y = fmaf(a0, w0.y, fmaf(a1, w1.y, fmaf(a2, w2.y, fmaf(a3, w3.y, acc[i][u].y))));
                    acc[i][u].z = fmaf(a0, w0.z, fmaf(a1, w1.z, fmaf(a2, w2.z, fmaf(a3, w3.z, acc[i][u].z))));
                    acc[i][u].w = fmaf(a0, w0.w, fmaf(a1, w1.w, fmaf(a2, w2.w, fmaf(a3, w3.w, acc[i][u].w))));
                }
            }
        }
#pragma unroll
        for (int i = 0; i < 4; i++) {
            float4* xo = Xout + (row0 + i) * 32 + c4;
            xo[0] = acc[i][0]; xo[8] = acc[i][1]; xo[16] = acc[i][2]; xo[24] = acc[i][3];
        }
    }
}

// ---------------------------------------------------------------------------
extern "C" void kernel_launch(void* const* d_in, const int* in_sizes, int n_in,
                              void* d_out, int out_size) {
    const float* X = (const float*)d_in[0];
    const long long* ei = (const long long*)d_in[1];
    const float* eps = (const float*)d_in[2];
    const float* W1 = (const float*)d_in[3];
    const float* b1 = (const float*)d_in[4];
    const float* g1 = (const float*)d_in[5];
    const float* bt1 = (const float*)d_in[6];
    const float* W2 = (const float*)d_in[7];
    const float* b2 = (const float*)d_in[8];
    const float* g2 = (const float*)d_in[9];
    const float* bt2 = (const float*)d_in[10];
    const float* W3 = (const float*)d_in[11];
    const float* b3 = (const float*)d_in[12];

    const int GB = 296;   // GEMM grid
    const int AB = 592;   // aggregation grid

    k_detect<<<1, 32>>>(ei);
    k_prep<<<392, 256>>>();
    k_hist<<<6250, 256>>>(ei);
    k_scanA<<<98, 1024>>>();
    k_scanB<<<1, 128>>>();
    k_scanC<<<392, 256>>>();
    k_fill<<<6250, 256>>>(ei);
    k_compose<<<3, 1024>>>(W1, W3, b3);

    k_gemm1<<<GB, 256>>>((const float4*)X, W1);   // U = X @ W1_0^T

    for (int l = 0; l < NL; l++) {
        k_agg32<<<AB, 256>>>(eps, l, b1 + l * HH);
        k_bn<<<1, 32>>>(1, g1 + l * HH, bt1 + l * HH);
        k_gemm32<<<GB, 256>>>(0, W2 + l * HH * HH, b2 + l * HH, -1, 1, 1);
        k_bn<<<1, 32>>>(2, g2 + l * HH, bt2 + l * HH);
        if (l < NL - 1) {
            k_gemm32<<<GB, 256>>>(1, (const float*)0, (const float*)0, l, 0, 2);
        } else {
            k_gemm3<<<GB, 256>>>(W3 + l * DD * HH, b3 + l * DD, (float4*)d_out);
        }
    }
}

// round 12
// speedup vs baseline: 4.0840x; 1.1130x over previous
#include <cuda_runtime.h>

#define NN 100000
#define NE 1600000
#define DD 128
#define HH 32
#define NL 4

// ---- scratch (static device memory; no allocation) ----
__device__ __align__(16) float g_U[NN * HH];   // projected features (32-dim)
__device__ __align__(16) float g_Y1[NN * HH];
__device__ __align__(16) float g_Y2[NN * HH];
__device__ __align__(16) float g_Wc[3 * HH * HH];  // composed W1_{l+1}@W3_l, [k*32+c]
__device__ __align__(16) float g_bc[3 * HH];       // composed bias W1_{l+1}@b3_l
__device__ double g_s1[NL][2 * HH];                // per-layer BN1 stats (sum, sumsq)
__device__ double g_s2[NL][2 * HH];                // per-layer BN2 stats
__device__ int g_ei64;
// CSR scratch
__device__ int g_deg[NN];
__device__ int g_off[NN + 1];
__device__ int g_cursor[NN];
__device__ int g_csr[NE];
__device__ int g_bsum[128];

// ---------------------------------------------------------------------------
// prep: zero degree + all per-layer stats; thread 0 detects edge dtype.
// ---------------------------------------------------------------------------
__global__ void k_prep(const long long* __restrict__ ei) {
    int gid = blockIdx.x * blockDim.x + threadIdx.x;
    if (gid == 0) {
        int is64 = 1;
        for (int i = 0; i < 16; i++) {
            long long v = ei[i];
            if (v < 0 || v >= (long long)NN) { is64 = 0; break; }
        }
        g_ei64 = is64;
    }
    if (gid < NN) g_deg[gid] = 0;
    if (gid < NL * 2 * HH) {
        ((double*)g_s1)[gid] = 0.0;
        ((double*)g_s2)[gid] = 0.0;
    }
}

__global__ void k_hist(const long long* __restrict__ ei) {
    int e = blockIdx.x * blockDim.x + threadIdx.x;
    if (e >= NE) return;
    int dst = g_ei64 ? (int)ei[NE + e] : ((const int*)ei)[NE + e];
    atomicAdd(&g_deg[dst], 1);
}

__global__ void k_scanA() {
    __shared__ int s[1024];
    int gid = blockIdx.x * 1024 + threadIdx.x;
    int v = (gid < NN) ? g_deg[gid] : 0;
    s[threadIdx.x] = v;
    __syncthreads();
    for (int d = 1; d < 1024; d <<= 1) {
        int t = (threadIdx.x >= d) ? s[threadIdx.x - d] : 0;
        __syncthreads();
        s[threadIdx.x] += t;
        __syncthreads();
    }
    if (gid < NN) g_cursor[gid] = s[threadIdx.x];
    if (threadIdx.x == 1023) g_bsum[blockIdx.x] = s[1023];
}

__global__ void k_scanB() {
    __shared__ int s[128];
    int v = (threadIdx.x < 98) ? g_bsum[threadIdx.x] : 0;
    s[threadIdx.x] = v;
    __syncthreads();
    for (int d = 1; d < 128; d <<= 1) {
        int t = (threadIdx.x >= d) ? s[threadIdx.x - d] : 0;
        __syncthreads();
        s[threadIdx.x] += t;
        __syncthreads();
    }
    g_bsum[threadIdx.x] = s[threadIdx.x];
}

__global__ void k_scanC() {
    int gid = blockIdx.x * blockDim.x + threadIdx.x;
    if (gid >= NN) return;
    int b = gid >> 10;
    int excl = g_cursor[gid] - g_deg[gid] + (b ? g_bsum[b - 1] : 0);
    g_off[gid] = excl;
    g_cursor[gid] = excl;
    if (gid == 0) g_off[NN] = NE;
}

__global__ void k_fill(const long long* __restrict__ ei) {
    int e = blockIdx.x * blockDim.x + threadIdx.x;
    if (e >= NE) return;
    int src, dst;
    if (g_ei64) { src = (int)ei[e]; dst = (int)ei[NE + e]; }
    else { src = ((const int*)ei)[e]; dst = ((const int*)ei)[NE + e]; }
    int pos = atomicAdd(&g_cursor[dst], 1);
    g_csr[pos] = src;
}

// ---------------------------------------------------------------------------
// Compose Wc_t = W1_{t+1} @ W3_t (stored [k*32+c]), bc_t = W1_{t+1} @ b3_t
// ---------------------------------------------------------------------------
__global__ void k_compose(const float* __restrict__ W1, const float* __restrict__ W3,
                          const float* __restrict__ b3) {
    int t = blockIdx.x;
    int tid = threadIdx.x;
    int c = tid >> 5, k = tid & 31;
    const float* w1 = W1 + (t + 1) * HH * DD + c * DD;
    const float* w3 = W3 + t * DD * HH;
    float acc = 0.f;
#pragma unroll 8
    for (int d = 0; d < DD; d++) acc = fmaf(w1[d], w3[d * HH + k], acc);
    g_Wc[t * HH * HH + k * HH + c] = acc;
    if (tid < HH) {
        const float* w1c = W1 + (t + 1) * HH * DD + tid * DD;
        const float* b3t = b3 + t * DD;
        float a = 0.f;
        for (int d = 0; d < DD; d++) a = fmaf(w1c[d], b3t[d], a);
        g_bc[t * HH + tid] = a;
    }
}

// ---------------------------------------------------------------------------
// Inline BN-fold helper: derive (a, c) for 4 columns col=4*c4+j from stats.
// ---------------------------------------------------------------------------
__device__ __forceinline__ void bn_fold(const double* st, const float* gam,
                                        const float* bet, int c4,
                                        float4& a4, float4& c4v) {
    const double invN = 1.0 / (double)NN;
    float a[4], c[4];
#pragma unroll
    for (int j = 0; j < 4; j++) {
        int col = 4 * c4 + j;
        double m = st[col] * invN;
        double var = st[HH + col] * invN - m * m;
        float aa = gam[col] * rsqrtf((float)var + 1e-5f);
        a[j] = aa;
        c[j] = bet[col] - aa * (float)m;
    }
    a4 = make_float4(a[0], a[1], a[2], a[3]);
    c4v = make_float4(c[0], c[1], c[2], c[3]);
}

// ---------------------------------------------------------------------------
// GEMM1: U = X_in @ W1_0^T  (128 -> 32), no bias, no stats.
// ---------------------------------------------------------------------------
__global__ __launch_bounds__(256) void k_gemm1(const float4* __restrict__ Xin,
                                               const float* __restrict__ W1l) {
    __shared__ __align__(16) float Ws[DD * HH];  // Ws[k*32+c] = W1l[c*128+k]
    for (int i = threadIdx.x; i < DD * HH; i += 256) {
        int k = i >> 5, c = i & 31;
        Ws[k * 32 + c] = W1l[c * DD + k];
    }
    __syncthreads();
    const float4* Ws4 = (const float4*)Ws;
    int lane = threadIdx.x & 31;
    int rr = lane >> 3, c4 = lane & 7, base = lane & 24;
    int gw = blockIdx.x * 8 + (threadIdx.x >> 5);
    int nw = gridDim.x * 8;
    for (int rb = gw * 16; rb < NN; rb += nw * 16) {
        int row0 = rb + 4 * rr;
        float4 z[4][4];
#pragma unroll
        for (int i = 0; i < 4; i++)
#pragma unroll
            for (int m = 0; m < 4; m++)
                z[i][m] = Xin[(row0 + i) * 32 + c4 + 8 * m];
        float4 acc[4] = {{0,0,0,0},{0,0,0,0},{0,0,0,0},{0,0,0,0}};
#pragma unroll
        for (int m = 0; m < 4; m++) {
#pragma unroll 4
            for (int kc2 = 0; kc2 < 8; kc2++) {
                int srcl = base | kc2;
                int kk = (m * 8 + kc2) * 4;
                float4 w0 = Ws4[(kk + 0) * 8 + c4];
                float4 w1 = Ws4[(kk + 1) * 8 + c4];
                float4 w2 = Ws4[(kk + 2) * 8 + c4];
                float4 w3 = Ws4[(kk + 3) * 8 + c4];
#pragma unroll
                for (int i = 0; i < 4; i++) {
                    float a0 = __shfl_sync(0xffffffffu, z[i][m].x, srcl);
                    float a1 = __shfl_sync(0xffffffffu, z[i][m].y, srcl);
                    float a2 = __shfl_sync(0xffffffffu, z[i][m].z, srcl);
                    float a3 = __shfl_sync(0xffffffffu, z[i][m].w, srcl);
                    acc[i].x = fmaf(a0, w0.x, fmaf(a1, w1.x, fmaf(a2, w2.x, fmaf(a3, w3.x, acc[i].x))));
                    acc[i].y = fmaf(a0, w0.y, fmaf(a1, w1.y, fmaf(a2, w2.y, fmaf(a3, w3.y, acc[i].y))));
                    acc[i].z = fmaf(a0, w0.z, fmaf(a1, w1.z, fmaf(a2, w2.z, fmaf(a3, w3.z, acc[i].z))));
                    acc[i].w = fmaf(a0, w0.w, fmaf(a1, w1.w, fmaf(a2, w2.w, fmaf(a3, w3.w, acc[i].w))));
                }
            }
        }
#pragma unroll
        for (int i = 0; i < 4; i++)
            ((float4*)g_U)[(row0 + i) * 8 + c4] = acc[i];
    }
}

// ---------------------------------------------------------------------------
// 32-dim aggregation: Y1[n] = (1+eps_l)*U[n] + sum_{s in N(n)} U[s] + b1
// Warp per node (grid-stride); lane = column. Accumulates g_s1[l].
// ---------------------------------------------------------------------------
__global__ __launch_bounds__(256) void k_agg32(const float* __restrict__ eps, int l,
                                               const float* __restrict__ b1l) {
    __shared__ float ssum[8][HH], ssq[8][HH];
    int warp = threadIdx.x >> 5, lane = threadIdx.x & 31;
    int gw = blockIdx.x * 8 + warp;
    int nw = gridDim.x * 8;
    float s = 1.0f + eps[l];
    float bias = b1l[lane];
    float lsum = 0.f, lsq = 0.f;
    for (int n = gw; n < NN; n += nw) {
        int beg = g_off[n], end = g_off[n + 1];
        float acc = fmaf(s, g_U[n * HH + lane], bias);
        int e = beg;
        for (; e + 8 <= end; e += 8) {
            int s0 = __ldg(&g_csr[e + 0]), s1 = __ldg(&g_csr[e + 1]);
            int s2 = __ldg(&g_csr[e + 2]), s3 = __ldg(&g_csr[e + 3]);
            int s4 = __ldg(&g_csr[e + 4]), s5 = __ldg(&g_csr[e + 5]);
            int s6 = __ldg(&g_csr[e + 6]), s7 = __ldg(&g_csr[e + 7]);
            float v0 = g_U[s0 * HH + lane], v1 = g_U[s1 * HH + lane];
            float v2 = g_U[s2 * HH + lane], v3 = g_U[s3 * HH + lane];
            float v4 = g_U[s4 * HH + lane], v5 = g_U[s5 * HH + lane];
            float v6 = g_U[s6 * HH + lane], v7 = g_U[s7 * HH + lane];
            acc += ((v0 + v1) + (v2 + v3)) + ((v4 + v5) + (v6 + v7));
        }
        for (; e + 2 <= end; e += 2) {
            int s0 = __ldg(&g_csr[e + 0]), s1 = __ldg(&g_csr[e + 1]);
            acc += g_U[s0 * HH + lane] + g_U[s1 * HH + lane];
        }
        if (e < end) acc += g_U[__ldg(&g_csr[e]) * HH + lane];
        g_Y1[n * HH + lane] = acc;
        lsum += acc;
        lsq = fmaf(acc, acc, lsq);
    }
    ssum[warp][lane] = lsum;
    ssq[warp][lane] = lsq;
    __syncthreads();
    if (threadIdx.x < HH) {
        float a = 0.f, q = 0.f;
        for (int w = 0; w < 8; w++) { a += ssum[w][threadIdx.x]; q += ssq[w][threadIdx.x]; }
        atomicAdd(&g_s1[l][threadIdx.x], (double)a);
        atomicAdd(&g_s1[l][HH + threadIdx.x], (double)q);
    }
}

// ---------------------------------------------------------------------------
// Generic 32->32: out = relu(bn(in)) @ W^T + bias, BN fold computed inline.
// io: 0 -> in=g_Y1, out=g_Y2 (bn from g_s1[l], stats accumulated into g_s2[l])
//     1 -> in=g_Y2, out=g_U  (bn from g_s2[l], no stats)
// trans >= 0: weight = g_Wc[trans], bias = g_bc[trans]; else W2l/b2l.
// ---------------------------------------------------------------------------
__global__ __launch_bounds__(256) void k_gemm32(int io, int l,
                                                const float* __restrict__ W2l,
                                                const float* __restrict__ b2l,
                                                const float* __restrict__ gam,
                                                const float* __restrict__ bet,
                                                int trans) {
    __shared__ __align__(16) float Ws[HH * HH];
    __shared__ float bsum[HH], bsq[HH];
    const float4* in = (io == 0) ? (const float4*)g_Y1 : (const float4*)g_Y2;
    float4* out = (io == 0) ? (float4*)g_Y2 : (float4*)g_U;
    const double* st = (io == 0) ? g_s1[l] : g_s2[l];
    int do_stats = (io == 0);
    if (trans >= 0) {
        for (int i = threadIdx.x; i < HH * HH; i += 256)
            Ws[i] = g_Wc[trans * HH * HH + i];
    } else {
        for (int i = threadIdx.x; i < HH * HH; i += 256) {
            int k = i >> 5, c = i & 31;
            Ws[k * 32 + c] = W2l[c * HH + k];
        }
    }
    if (threadIdx.x < HH) { bsum[threadIdx.x] = 0.f; bsq[threadIdx.x] = 0.f; }
    __syncthreads();
    const float4* Ws4 = (const float4*)Ws;
    int lane = threadIdx.x & 31;
    int rr = lane >> 3, c4 = lane & 7, base = lane & 24;
    int gw = blockIdx.x * 8 + (threadIdx.x >> 5);
    int nw = gridDim.x * 8;
    float4 bias = (trans >= 0) ? ((const float4*)(g_bc + trans * HH))[c4]
                               : ((const float4*)b2l)[c4];
    float4 ba, bc;
    bn_fold(st, gam, bet, c4, ba, bc);
    float4 ls = {0, 0, 0, 0}, lq = {0, 0, 0, 0};
    for (int rb = gw * 16; rb < NN; rb += nw * 16) {
        int row0 = rb + 4 * rr;
        float4 h[4];
#pragma unroll
        for (int i = 0; i < 4; i++) {
            float4 y = in[(row0 + i) * 8 + c4];
            h[i].x = fmaxf(fmaf(ba.x, y.x, bc.x), 0.f);
            h[i].y = fmaxf(fmaf(ba.y, y.y, bc.y), 0.f);
            h[i].z = fmaxf(fmaf(ba.z, y.z, bc.z), 0.f);
            h[i].w = fmaxf(fmaf(ba.w, y.w, bc.w), 0.f);
        }
        float4 acc[4] = {bias, bias, bias, bias};
#pragma unroll 4
        for (int kc2 = 0; kc2 < 8; kc2++) {
            int srcl = base | kc2;
            int kk = kc2 * 4;
            float4 w0 = Ws4[(kk + 0) * 8 + c4];
            float4 w1 = Ws4[(kk + 1) * 8 + c4];
            float4 w2 = Ws4[(kk + 2) * 8 + c4];
            float4 w3 = Ws4[(kk + 3) * 8 + c4];
#pragma unroll
            for (int i = 0; i < 4; i++) {
                float a0 = __shfl_sync(0xffffffffu, h[i].x, srcl);
                float a1 = __shfl_sync(0xffffffffu, h[i].y, srcl);
                float a2 = __shfl_sync(0xffffffffu, h[i].z, srcl);
                float a3 = __shfl_sync(0xffffffffu, h[i].w, srcl);
                acc[i].x = fmaf(a0, w0.x, fmaf(a1, w1.x, fmaf(a2, w2.x, fmaf(a3, w3.x, acc[i].x))));
                acc[i].y = fmaf(a0, w0.y, fmaf(a1, w1.y, fmaf(a2, w2.y, fmaf(a3, w3.y, acc[i].y))));
                acc[i].z = fmaf(a0, w0.z, fmaf(a1, w1.z, fmaf(a2, w2.z, fmaf(a3, w3.z, acc[i].z))));
                acc[i].w = fmaf(a0, w0.w, fmaf(a1, w1.w, fmaf(a2, w2.w, fmaf(a3, w3.w, acc[i].w))));
            }
        }
#pragma unroll
        for (int i = 0; i < 4; i++) {
            out[(row0 + i) * 8 + c4] = acc[i];
            if (do_stats) {
                ls.x += acc[i].x; ls.y += acc[i].y; ls.z += acc[i].z; ls.w += acc[i].w;
                lq.x = fmaf(acc[i].x, acc[i].x, lq.x); lq.y = fmaf(acc[i].y, acc[i].y, lq.y);
                lq.z = fmaf(acc[i].z, acc[i].z, lq.z); lq.w = fmaf(acc[i].w, acc[i].w, lq.w);
            }
        }
    }
    if (do_stats) {
        atomicAdd(&bsum[4 * c4 + 0], ls.x); atomicAdd(&bsum[4 * c4 + 1], ls.y);
        atomicAdd(&bsum[4 * c4 + 2], ls.z); atomicAdd(&bsum[4 * c4 + 3], ls.w);
        atomicAdd(&bsq[4 * c4 + 0], lq.x);  atomicAdd(&bsq[4 * c4 + 1], lq.y);
        atomicAdd(&bsq[4 * c4 + 2], lq.z);  atomicAdd(&bsq[4 * c4 + 3], lq.w);
        __syncthreads();
        if (threadIdx.x < HH) {
            atomicAdd(&g_s2[l][threadIdx.x], (double)bsum[threadIdx.x]);
            atomicAdd(&g_s2[l][HH + threadIdx.x], (double)bsq[threadIdx.x]);
        }
    }
}

// ---------------------------------------------------------------------------
// Final GEMM3: out = relu(bn2(Y2)) @ W3^T + b3  (32 -> 128), BN2 inline.
// ---------------------------------------------------------------------------
__global__ __launch_bounds__(256) void k_gemm3(int l,
                                               const float* __restrict__ W3l,
                                               const float* __restrict__ b3l,
                                               const float* __restrict__ gam,
                                               const float* __restrict__ bet,
                                               float4* __restrict__ Xout) {
    __shared__ __align__(16) float Wt[HH * DD];  // Wt[k*128+c] = W3l[c*32+k]
    for (int i = threadIdx.x; i < HH * DD; i += 256) {
        int c = i >> 5, k = i & 31;
        Wt[k * DD + c] = W3l[i];
    }
    __syncthreads();
    const float4* Wt4 = (const float4*)Wt;
    int lane = threadIdx.x & 31;
    int rr = lane >> 3, c4 = lane & 7, base = lane & 24;
    int gw = blockIdx.x * 8 + (threadIdx.x >> 5);
    int nw = gridDim.x * 8;
    float4 ba, bc;
    bn_fold(g_s2[l], gam, bet, c4, ba, bc);
    float4 bias[4];
#pragma unroll
    for (int u = 0; u < 4; u++) bias[u] = ((const float4*)b3l)[c4 + 8 * u];
    for (int rb = gw * 16; rb < NN; rb += nw * 16) {
        int row0 = rb + 4 * rr;
        float4 h[4];
#pragma unroll
        for (int i = 0; i < 4; i++) {
            float4 y = ((const float4*)g_Y2)[(row0 + i) * 8 + c4];
            h[i].x = fmaxf(fmaf(ba.x, y.x, bc.x), 0.f);
            h[i].y = fmaxf(fmaf(ba.y, y.y, bc.y), 0.f);
            h[i].z = fmaxf(fmaf(ba.z, y.z, bc.z), 0.f);
            h[i].w = fmaxf(fmaf(ba.w, y.w, bc.w), 0.f);
        }
        float4 acc[4][4];
#pragma unroll
        for (int i = 0; i < 4; i++)
#pragma unroll
            for (int u = 0; u < 4; u++) acc[i][u] = bias[u];
        for (int kc2 = 0; kc2 < 8; kc2++) {
            int srcl = base | kc2;
            int kk = kc2 * 4;
#pragma unroll
            for (int i = 0; i < 4; i++) {
                float a0 = __shfl_sync(0xffffffffu, h[i].x, srcl);
                float a1 = __shfl_sync(0xffffffffu, h[i].y, srcl);
                float a2 = __shfl_sync(0xffffffffu, h[i].z, srcl);
                float a3 = __shfl_sync(0xffffffffu, h[i].w, srcl);
#pragma unroll
                for (int u = 0; u < 4; u++) {
                    float4 w0 = Wt4[(kk + 0) * 32 + c4 + 8 * u];
                    float4 w1 = Wt4[(kk + 1) * 32 + c4 + 8 * u];
                    float4 w2 = Wt4[(kk + 2) * 32 + c4 + 8 * u];
                    float4 w3 = Wt4[(kk + 3) * 32 + c4 + 8 * u];
                    acc[i][u].x = fmaf(a0, w0.x, fmaf(a1, w1.x, fmaf(a2, w2.x, fmaf(a3, w3.x, acc[i][u].x))));
                    acc[i][u].y = fmaf(a0, w0.y, fmaf(a1, w1.y, fmaf(a2, w2.y, fmaf(a3, w3.y, acc[i][u].y))));
                    acc[i][u].z = fmaf(a0, w0.z, fmaf(a1, w1.z, fmaf(a2, w2.z, fmaf(a3, w3.z, acc[i][u].z))));
                    acc[i][u].w = fmaf(a0, w0.w, fmaf(a1, w1.w, fmaf(a2, w2.w, fmaf(a3, w3.w, acc[i][u].w))));
                }
            }
        }
#pragma unroll
        for (int i = 0; i < 4; i++) {
            float4* xo = Xout + (row0 + i) * 32 + c4;
            xo[0] = acc[i][0]; xo[8] = acc[i][1]; xo[16] = acc[i][2]; xo[24] = acc[i][3];
        }
    }
}

// ---------------------------------------------------------------------------
extern "C" void kernel_launch(void* const* d_in, const int* in_sizes, int n_in,
                              void* d_out, int out_size) {
    const float* X = (const float*)d_in[0];
    const long long* ei = (const long long*)d_in[1];
    const float* eps = (const float*)d_in[2];
    const float* W1 = (const float*)d_in[3];
    const float* b1 = (const float*)d_in[4];
    const float* g1 = (const float*)d_in[5];
    const float* bt1 = (const float*)d_in[6];
    const float* W2 = (const float*)d_in[7];
    const float* b2 = (const float*)d_in[8];
    const float* g2 = (const float*)d_in[9];
    const float* bt2 = (const float*)d_in[10];
    const float* W3 = (const float*)d_in[11];
    const float* b3 = (const float*)d_in[12];

    const int GB = 296;    // GEMM grid
    const int AB = 1184;   // aggregation grid

    k_prep<<<392, 256>>>(ei);
    k_hist<<<6250, 256>>>(ei);
    k_scanA<<<98, 1024>>>();
    k_scanB<<<1, 128>>>();
    k_scanC<<<392, 256>>>();
    k_fill<<<6250, 256>>>(ei);
    k_compose<<<3, 1024>>>(W1, W3, b3);

    k_gemm1<<<GB, 256>>>((const float4*)X, W1);   // U = X @ W1_0^T

    for (int l = 0; l < NL; l++) {
        k_agg32<<<AB, 256>>>(eps, l, b1 + l * HH);
        k_gemm32<<<GB, 256>>>(0, l, W2 + l * HH * HH, b2 + l * HH,
                              g1 + l * HH, bt1 + l * HH, -1);
        if (l < NL - 1) {
            k_gemm32<<<GB, 256>>>(1, l, (const float*)0, (const float*)0,
                                  g2 + l * HH, bt2 + l * HH, l);
        } else {
            k_gemm3<<<GB, 256>>>(l, W3 + l * DD * HH, b3 + l * DD,
                                 g2 + l * HH, bt2 + l * HH, (float4*)d_out);
        }
    }
}